// round 3
// baseline (speedup 1.0000x reference)
#include <cuda_runtime.h>
#include <math.h>

#define Bb 8
#define Ss 1024
#define Hh 1024
#define BS (Bb*Ss)   // 8192

// ---------------- scratch (device globals; no allocation allowed) ----------------
__device__ float g_cn[(size_t)BS*Hh];   // layernorm output
__device__ float g_q [(size_t)BS*Hh];
__device__ float g_k [(size_t)BS*Hh];
__device__ float g_sup[BS];
__device__ float g_sdn[BS];
__device__ float g_pup[BS];
__device__ float g_pdn[BS];
__device__ float g_band[BS];            // band[b*S+i] = neibor_sym at (i,i+1), valid i<S-1

// ---------------- LayerNorm: one block (256 thr) per row ----------------
__global__ __launch_bounds__(256) void ln_kernel(const float* __restrict__ x,
                                                 const float* __restrict__ gamma,
                                                 const float* __restrict__ beta) {
    int row = blockIdx.x;
    int tid = threadIdx.x;
    const float4* xr = (const float4*)(x + (size_t)row * Hh);
    float4 v = xr[tid];

    __shared__ float red[8];
    // mean
    float s = v.x + v.y + v.z + v.w;
    #pragma unroll
    for (int o = 16; o; o >>= 1) s += __shfl_xor_sync(0xffffffffu, s, o);
    if ((tid & 31) == 0) red[tid >> 5] = s;
    __syncthreads();
    if (tid < 8) {
        float t = red[tid];
        #pragma unroll
        for (int o = 4; o; o >>= 1) t += __shfl_xor_sync(0xffu, t, o);
        if (tid == 0) red[0] = t;
    }
    __syncthreads();
    float mu = red[0] * (1.0f / Hh);
    __syncthreads();
    // variance
    float dx = v.x - mu, dy = v.y - mu, dz = v.z - mu, dw = v.w - mu;
    float ss = dx*dx + dy*dy + dz*dz + dw*dw;
    #pragma unroll
    for (int o = 16; o; o >>= 1) ss += __shfl_xor_sync(0xffffffffu, ss, o);
    if ((tid & 31) == 0) red[tid >> 5] = ss;
    __syncthreads();
    if (tid < 8) {
        float t = red[tid];
        #pragma unroll
        for (int o = 4; o; o >>= 1) t += __shfl_xor_sync(0xffu, t, o);
        if (tid == 0) red[0] = t;
    }
    __syncthreads();
    float var = red[0] * (1.0f / Hh);
    float rstd = rsqrtf(var + 1e-5f);

    float4 gm = ((const float4*)gamma)[tid];
    float4 bt = ((const float4*)beta)[tid];
    float4 o4;
    o4.x = dx * rstd * gm.x + bt.x;
    o4.y = dy * rstd * gm.y + bt.y;
    o4.z = dz * rstd * gm.z + bt.z;
    o4.w = dw * rstd * gm.w + bt.w;
    ((float4*)(g_cn + (size_t)row * Hh))[tid] = o4;
}

// ---------------- fp32 SGEMM (NN): C[M,1024] = A[M,1024] @ W[1024,1024] + bias ----------------
__global__ __launch_bounds__(256) void sgemm_nn(const float* __restrict__ A,
                                                const float* __restrict__ W,
                                                const float* __restrict__ bias,
                                                float* __restrict__ C) {
    const int N = 1024, K = 1024;
    __shared__ float As[16][132];
    __shared__ float Bs[16][128];

    int bm = blockIdx.y, bn = blockIdx.x;
    int tid = threadIdx.x;
    int tx = tid & 15, ty = tid >> 4;

    float acc[8][8];
    #pragma unroll
    for (int i = 0; i < 8; i++)
        #pragma unroll
        for (int j = 0; j < 8; j++) acc[i][j] = 0.f;

    const float* Ab = A + (size_t)bm * 128 * K;
    const float* Wb = W + bn * 128;

    for (int k0 = 0; k0 < K; k0 += 16) {
        #pragma unroll
        for (int r = 0; r < 2; r++) {
            int f  = tid + r * 256;       // 0..511 float4s of A tile
            int m  = f >> 2;              // 0..127
            int kk = (f & 3) * 4;
            float4 a = *(const float4*)(Ab + (size_t)m * K + k0 + kk);
            As[kk + 0][m] = a.x;
            As[kk + 1][m] = a.y;
            As[kk + 2][m] = a.z;
            As[kk + 3][m] = a.w;
        }
        #pragma unroll
        for (int r = 0; r < 2; r++) {
            int f  = tid + r * 256;
            int kk = f >> 5;              // 0..15
            int n4 = (f & 31) * 4;
            *(float4*)(&Bs[kk][n4]) = *(const float4*)(Wb + (size_t)(k0 + kk) * N + n4);
        }
        __syncthreads();
        #pragma unroll
        for (int kk = 0; kk < 16; kk++) {
            float a[8], b[8];
            *(float4*)(a)     = *(const float4*)(&As[kk][ty * 8]);
            *(float4*)(a + 4) = *(const float4*)(&As[kk][ty * 8 + 4]);
            *(float4*)(b)     = *(const float4*)(&Bs[kk][tx * 8]);
            *(float4*)(b + 4) = *(const float4*)(&Bs[kk][tx * 8 + 4]);
            #pragma unroll
            for (int i = 0; i < 8; i++)
                #pragma unroll
                for (int j = 0; j < 8; j++)
                    acc[i][j] += a[i] * b[j];
        }
        __syncthreads();
    }

    int row0 = bm * 128 + ty * 8;
    int col0 = bn * 128 + tx * 8;
    float4 b0 = *(const float4*)(bias + col0);
    float4 b1 = *(const float4*)(bias + col0 + 4);
    #pragma unroll
    for (int i = 0; i < 8; i++) {
        float4 o0, o1;
        o0.x = acc[i][0] + b0.x; o0.y = acc[i][1] + b0.y;
        o0.z = acc[i][2] + b0.z; o0.w = acc[i][3] + b0.w;
        o1.x = acc[i][4] + b1.x; o1.y = acc[i][5] + b1.y;
        o1.z = acc[i][6] + b1.z; o1.w = acc[i][7] + b1.w;
        *(float4*)(C + (size_t)(row0 + i) * N + col0)     = o0;
        *(float4*)(C + (size_t)(row0 + i) * N + col0 + 4) = o1;
    }
}

// ---------------- adjacent-pair scores: one warp per (b,i) ----------------
__global__ __launch_bounds__(256) void band_dots_kernel(const int* __restrict__ mask) {
    int gw = (blockIdx.x * blockDim.x + threadIdx.x) >> 5;
    int lane = threadIdx.x & 31;
    if (gw >= BS) return;
    int b = gw >> 10;
    int i = gw & (Ss - 1);
    const float* qi = g_q + (size_t)gw * Hh;
    int padi = mask[(b << 10) + i];
    float su = -1e9f, sd = -1e9f;

    if (i < Ss - 1 && padi && mask[(b << 10) + i + 1]) {
        const float* kj = g_k + (size_t)(gw + 1) * Hh;
        float acc = 0.f;
        #pragma unroll
        for (int it = 0; it < 8; it++) {
            int c = it * 128 + lane * 4;
            float4 a = *(const float4*)(qi + c);
            float4 v = *(const float4*)(kj + c);
            acc += a.x * v.x + a.y * v.y + a.z * v.z + a.w * v.w;
        }
        #pragma unroll
        for (int o = 16; o; o >>= 1) acc += __shfl_xor_sync(0xffffffffu, acc, o);
        su = acc * (1.0f / 32.0f);   // / sqrt(H)
    }
    if (i > 0 && padi && mask[(b << 10) + i - 1]) {
        const float* kj = g_k + (size_t)(gw - 1) * Hh;
        float acc = 0.f;
        #pragma unroll
        for (int it = 0; it < 8; it++) {
            int c = it * 128 + lane * 4;
            float4 a = *(const float4*)(qi + c);
            float4 v = *(const float4*)(kj + c);
            acc += a.x * v.x + a.y * v.y + a.z * v.z + a.w * v.w;
        }
        #pragma unroll
        for (int o = 16; o; o >>= 1) acc += __shfl_xor_sync(0xffffffffu, acc, o);
        sd = acc * (1.0f / 32.0f);
    }
    if (lane == 0) { g_sup[gw] = su; g_sdn[gw] = sd; }
}

// ---------------- 2-entry softmax per row ----------------
__global__ void probs_kernel() {
    int idx = blockIdx.x * blockDim.x + threadIdx.x;
    if (idx >= BS) return;
    float su = g_sup[idx], sd = g_sdn[idx];
    float m = fmaxf(su, sd);
    float eu = expf(su - m);
    float ed = expf(sd - m);
    float z = eu + ed;
    g_pup[idx] = eu / z;
    g_pdn[idx] = ed / z;
}

// ---------------- symmetric band values ----------------
__global__ void band_kernel() {
    int idx = blockIdx.x * blockDim.x + threadIdx.x;
    if (idx >= BS) return;
    int i = idx & (Ss - 1);
    if (i < Ss - 1)
        g_band[idx] = sqrtf(g_pup[idx] * g_pdn[idx + 1] + 1e-9f);
}

// ---------------- fused output: one block per (b,row) ----------------
__global__ __launch_bounds__(256) void out_kernel(const float* __restrict__ prior,
                                                  const int* __restrict__ mask,
                                                  float* __restrict__ out,
                                                  int Nout) {
    int row = blockIdx.x;               // 0..BS-1
    int b = row >> 10;
    int r = row & (Ss - 1);
    int tid = threadIdx.x;
    const float c0 = sqrtf(1e-9f);

    float4 p4 = ((const float4*)(prior + (size_t)row * Ss))[tid];
    int4  m4 = ((const int4*)(mask + (b << 10)))[tid];
    int padr = mask[(b << 10) + r];

    float pv[4] = {p4.x, p4.y, p4.z, p4.w};
    int   mc[4] = {m4.x, m4.y, m4.z, m4.w};
    int c_base = tid * 4;

    float nbo[4], graw[4];
    #pragma unroll
    for (int j = 0; j < 4; j++) {
        int c = c_base + j;
        float nbs = c0;
        if (r > 0 && c == r - 1)       nbs = g_band[(b << 10) + r - 1];
        if (r < Ss - 1 && c == r + 1)  nbs = g_band[(b << 10) + r];
        nbo[j]  = pv[j] + (1.0f - pv[j]) * nbs;
        graw[j] = (c == r) ? (2.0f + 1e-9f) : (1.0f + nbo[j]);
    }

    // block row-sum of graw
    __shared__ float red[8];
    float s = graw[0] + graw[1] + graw[2] + graw[3];
    #pragma unroll
    for (int o = 16; o; o >>= 1) s += __shfl_xor_sync(0xffffffffu, s, o);
    if ((tid & 31) == 0) red[tid >> 5] = s;
    __syncthreads();
    if (tid < 8) {
        float t = red[tid];
        #pragma unroll
        for (int o = 4; o; o >>= 1) t += __shfl_xor_sync(0xffu, t, o);
        if (tid == 0) red[0] = t;
    }
    __syncthreads();
    float invD = 1.0f / (red[0] + 1e-9f);

    float4 go, no;
    float f0 = (padr && mc[0]) ? 1.0f : 0.0f;
    float f1 = (padr && mc[1]) ? 1.0f : 0.0f;
    float f2 = (padr && mc[2]) ? 1.0f : 0.0f;
    float f3 = (padr && mc[3]) ? 1.0f : 0.0f;
    go.x = graw[0] * invD * f0; no.x = nbo[0] * f0;
    go.y = graw[1] * invD * f1; no.y = nbo[1] * f1;
    go.z = graw[2] * invD * f2; no.z = nbo[2] * f2;
    go.w = graw[3] * invD * f3; no.w = nbo[3] * f3;

    size_t base = (size_t)row * Ss + c_base;
    *(float4*)(out + base)                = go;   // g
    *(float4*)(out + (size_t)Nout + base) = no;   // neibor
}

// ---------------- launch ----------------
extern "C" void kernel_launch(void* const* d_in, const int* in_sizes, int n_in,
                              void* d_out, int out_size) {
    const float* context = (const float*)d_in[0];
    const int*   mask    = (const int*)  d_in[1];
    const float* prior   = (const float*)d_in[2];
    const float* gamma   = (const float*)d_in[3];
    const float* beta    = (const float*)d_in[4];
    const float* Wk      = (const float*)d_in[5];
    const float* bk      = (const float*)d_in[6];
    const float* Wq      = (const float*)d_in[7];
    const float* bq      = (const float*)d_in[8];
    float* out = (float*)d_out;
    int Nout = out_size / 2;

    float *cn, *q, *k;
    cudaGetSymbolAddress((void**)&cn, g_cn);
    cudaGetSymbolAddress((void**)&q,  g_q);
    cudaGetSymbolAddress((void**)&k,  g_k);

    ln_kernel<<<BS, 256>>>(context, gamma, beta);

    dim3 ggrid(Hh / 128, BS / 128);   // (8, 64)
    sgemm_nn<<<ggrid, 256>>>(cn, Wq, bq, q);
    sgemm_nn<<<ggrid, 256>>>(cn, Wk, bk, k);

    band_dots_kernel<<<(BS * 32) / 256, 256>>>(mask);
    probs_kernel<<<(BS + 255) / 256, 256>>>();
    band_kernel<<<(BS + 255) / 256, 256>>>();

    out_kernel<<<BS, 256>>>(prior, mask, out, Nout);
}

// round 4
// speedup vs baseline: 4.2147x; 4.2147x over previous
#include <cuda_runtime.h>
#include <math.h>
#include <stdint.h>

#define Bb 8
#define Ss 1024
#define Hh 1024
#define BS (Bb*Ss)   // 8192

// ---------------- scratch (device globals; no allocation allowed) ----------------
__device__ float g_cn[(size_t)BS*Hh];    // layernorm output
__device__ float g_u [(size_t)BS*Hh];    // u = cn @ (Wq Wk^T)
__device__ float g_At[(size_t)Hh*Hh];    // At = Wk @ Wq^T  (= (Wq Wk^T)^T)
__device__ float g_wqb[Hh];              // Wq @ bk
__device__ float g_wkb[Hh];              // Wk @ bq
__device__ float g_bqbk;
__device__ float g_vq[BS];
__device__ float g_vk[BS];
__device__ float g_sup[BS];
__device__ float g_sdn[BS];
__device__ float g_pup[BS];
__device__ float g_pdn[BS];
__device__ float g_band[BS];

// ---------------- LayerNorm: one block (256 thr) per row ----------------
__global__ __launch_bounds__(256) void ln_kernel(const float* __restrict__ x,
                                                 const float* __restrict__ gamma,
                                                 const float* __restrict__ beta) {
    int row = blockIdx.x;
    int tid = threadIdx.x;
    const float4* xr = (const float4*)(x + (size_t)row * Hh);
    float4 v = xr[tid];

    __shared__ float red[8];
    float s = v.x + v.y + v.z + v.w;
    #pragma unroll
    for (int o = 16; o; o >>= 1) s += __shfl_xor_sync(0xffffffffu, s, o);
    if ((tid & 31) == 0) red[tid >> 5] = s;
    __syncthreads();
    if (tid < 8) {
        float t = red[tid];
        #pragma unroll
        for (int o = 4; o; o >>= 1) t += __shfl_xor_sync(0xffu, t, o);
        if (tid == 0) red[0] = t;
    }
    __syncthreads();
    float mu = red[0] * (1.0f / Hh);
    __syncthreads();
    float dx = v.x - mu, dy = v.y - mu, dz = v.z - mu, dw = v.w - mu;
    float ss = dx*dx + dy*dy + dz*dz + dw*dw;
    #pragma unroll
    for (int o = 16; o; o >>= 1) ss += __shfl_xor_sync(0xffffffffu, ss, o);
    if ((tid & 31) == 0) red[tid >> 5] = ss;
    __syncthreads();
    if (tid < 8) {
        float t = red[tid];
        #pragma unroll
        for (int o = 4; o; o >>= 1) t += __shfl_xor_sync(0xffu, t, o);
        if (tid == 0) red[0] = t;
    }
    __syncthreads();
    float var = red[0] * (1.0f / Hh);
    float rstd = rsqrtf(var + 1e-5f);

    float4 gm = ((const float4*)gamma)[tid];
    float4 bt = ((const float4*)beta)[tid];
    float4 o4;
    o4.x = dx * rstd * gm.x + bt.x;
    o4.y = dy * rstd * gm.y + bt.y;
    o4.z = dz * rstd * gm.z + bt.z;
    o4.w = dw * rstd * gm.w + bt.w;
    ((float4*)(g_cn + (size_t)row * Hh))[tid] = o4;
}

// ---------------- tf32 tensor-core NT GEMM: C[M,N] = Aop[M,K] * Bop[N,K]^T ----------------
// 128x128 block tile, 32-K tiles, 8 warps (2x4) of 64x32 warp tiles, cp.async
// double buffering, XOR swizzle (conflict-free fragment LDS).

__device__ __forceinline__ void cp16(uint32_t dst, const void* src) {
    asm volatile("cp.async.cg.shared.global [%0], [%1], 16;\n" :: "r"(dst), "l"(src));
}

#define MMA_TF32(d, a, b)                                                     \
    asm volatile("mma.sync.aligned.m16n8k8.row.col.f32.tf32.tf32.f32 "        \
                 "{%0,%1,%2,%3},{%4,%5,%6,%7},{%8,%9},{%0,%1,%2,%3};\n"       \
                 : "+f"(d[0]), "+f"(d[1]), "+f"(d[2]), "+f"(d[3])             \
                 : "r"(a[0]), "r"(a[1]), "r"(a[2]), "r"(a[3]),                \
                   "r"(b[0]), "r"(b[1]))

__global__ __launch_bounds__(256, 2) void gemm_tf32_nt(const float* __restrict__ Aop,
                                                       const float* __restrict__ Bop,
                                                       float* __restrict__ C,
                                                       int N, int K) {
    extern __shared__ float smem[];          // [As 2x4096][Bs 2x4096]
    const int TILEF = 128 * 32;              // floats per stage
    int tid = threadIdx.x;
    int lane = tid & 31, warp = tid >> 5;
    int wy = warp >> 2, wx = warp & 3;       // 2 x 4 warp grid

    const float* Abase = Aop + (size_t)blockIdx.y * 128 * K;
    const float* Bbase = Bop + (size_t)blockIdx.x * 128 * K;

    uint32_t sbase = (uint32_t)__cvta_generic_to_shared(smem);
    const uint32_t A_OFF = 0;
    const uint32_t B_OFF = 2u * TILEF * 4u;
    const uint32_t STAGE = TILEF * 4u;

    float acc[4][4][4];
    #pragma unroll
    for (int i = 0; i < 4; i++)
        #pragma unroll
        for (int j = 0; j < 4; j++)
            #pragma unroll
            for (int r = 0; r < 4; r++) acc[i][j][r] = 0.f;

    // load mapping: thread handles rows (tid>>3)+32r, 16B chunk (tid&7)
    int mrow = tid >> 3;
    int c4   = tid & 7;
    int c4x  = c4 ^ (mrow & 7);              // xor swizzle on 16B granules
    const float* Asrc = Abase + (size_t)mrow * K + 4 * c4;
    const float* Bsrc = Bbase + (size_t)mrow * K + 4 * c4;
    uint32_t Adst = sbase + A_OFF + (uint32_t)(mrow * 32 + 4 * c4x) * 4u;
    uint32_t Bdst = sbase + B_OFF + (uint32_t)(mrow * 32 + 4 * c4x) * 4u;

    int ntiles = K >> 5;

    // prologue
    {
        #pragma unroll
        for (int r = 0; r < 4; r++) {
            cp16(Adst + r * 32 * 32 * 4, Asrc + (size_t)(32 * r) * K);
            cp16(Bdst + r * 32 * 32 * 4, Bsrc + (size_t)(32 * r) * K);
        }
        asm volatile("cp.async.commit_group;\n");
        asm volatile("cp.async.wait_group 0;\n");
        __syncthreads();
    }

    int q = lane >> 2, rsel = lane & 3;
    int sw = 4 * q;

    for (int t = 0; t < ntiles; t++) {
        int cur = t & 1;
        if (t + 1 < ntiles) {
            int k0 = (t + 1) << 5;
            uint32_t so = (uint32_t)(1 - cur) * STAGE;
            #pragma unroll
            for (int r = 0; r < 4; r++) {
                cp16(Adst + so + r * 32 * 32 * 4, Asrc + (size_t)(32 * r) * K + k0);
                cp16(Bdst + so + r * 32 * 32 * 4, Bsrc + (size_t)(32 * r) * K + k0);
            }
            asm volatile("cp.async.commit_group;\n");
        }

        const uint32_t* sA = (const uint32_t*)(smem + cur * TILEF);
        const uint32_t* sB = (const uint32_t*)(smem + 2 * TILEF + cur * TILEF);

        #pragma unroll
        for (int kk = 0; kk < 32; kk += 8) {
            int col0 = (kk + rsel) ^ sw;
            int col1 = col0 ^ 4;
            uint32_t a[4][4], b[4][2];
            #pragma unroll
            for (int mt = 0; mt < 4; mt++) {
                int m0 = wy * 64 + mt * 16 + q;
                a[mt][0] = sA[m0 * 32 + col0];
                a[mt][1] = sA[(m0 + 8) * 32 + col0];
                a[mt][2] = sA[m0 * 32 + col1];
                a[mt][3] = sA[(m0 + 8) * 32 + col1];
            }
            #pragma unroll
            for (int nt = 0; nt < 4; nt++) {
                int n0 = wx * 32 + nt * 8 + q;
                b[nt][0] = sB[n0 * 32 + col0];
                b[nt][1] = sB[n0 * 32 + col1];
            }
            #pragma unroll
            for (int mt = 0; mt < 4; mt++)
                #pragma unroll
                for (int nt = 0; nt < 4; nt++)
                    MMA_TF32(acc[mt][nt], a[mt], b[nt]);
        }

        asm volatile("cp.async.wait_group 0;\n");
        __syncthreads();
    }

    // epilogue
    #pragma unroll
    for (int mt = 0; mt < 4; mt++) {
        int r0 = blockIdx.y * 128 + wy * 64 + mt * 16 + (lane >> 2);
        #pragma unroll
        for (int nt = 0; nt < 4; nt++) {
            int cc = blockIdx.x * 128 + wx * 32 + nt * 8 + 2 * (lane & 3);
            *(float2*)(C + (size_t)r0 * N + cc)       = make_float2(acc[mt][nt][0], acc[mt][nt][1]);
            *(float2*)(C + (size_t)(r0 + 8) * N + cc) = make_float2(acc[mt][nt][2], acc[mt][nt][3]);
        }
    }
}

// ---------------- bias precompute: wqb = Wq@bk, wkb = Wk@bq, bqbk = bq.bk ----------------
__global__ __launch_bounds__(256) void bias_prep(const float* __restrict__ Wq,
                                                 const float* __restrict__ bk,
                                                 const float* __restrict__ Wk,
                                                 const float* __restrict__ bq) {
    int gw = (blockIdx.x * blockDim.x + threadIdx.x) >> 5;
    int lane = threadIdx.x & 31;
    if (gw > 2048) return;
    const float* row; const float* vec;
    if (gw < 1024)      { row = Wq + (size_t)gw * Hh;          vec = bk; }
    else if (gw < 2048) { row = Wk + (size_t)(gw - 1024) * Hh; vec = bq; }
    else                { row = bq;                            vec = bk; }
    float acc = 0.f;
    #pragma unroll
    for (int it = 0; it < 8; it++) {
        int c = it * 128 + lane * 4;
        float4 a = *(const float4*)(row + c);
        float4 v = *(const float4*)(vec + c);
        acc += a.x * v.x + a.y * v.y + a.z * v.z + a.w * v.w;
    }
    #pragma unroll
    for (int o = 16; o; o >>= 1) acc += __shfl_xor_sync(0xffffffffu, acc, o);
    if (lane == 0) {
        if (gw < 1024)      g_wqb[gw] = acc;
        else if (gw < 2048) g_wkb[gw - 1024] = acc;
        else                g_bqbk = acc;
    }
}

// ---------------- vq_i = cn_i . wqb, vk_i = cn_i . wkb (one warp/row) ----------------
__global__ __launch_bounds__(256) void vqvk_kernel() {
    int gw = (blockIdx.x * blockDim.x + threadIdx.x) >> 5;
    int lane = threadIdx.x & 31;
    if (gw >= BS) return;
    const float* cni = g_cn + (size_t)gw * Hh;
    float aq = 0.f, ak = 0.f;
    #pragma unroll
    for (int it = 0; it < 8; it++) {
        int c = it * 128 + lane * 4;
        float4 x  = *(const float4*)(cni + c);
        float4 wq = *(const float4*)(g_wqb + c);
        float4 wk = *(const float4*)(g_wkb + c);
        aq += x.x * wq.x + x.y * wq.y + x.z * wq.z + x.w * wq.w;
        ak += x.x * wk.x + x.y * wk.y + x.z * wk.z + x.w * wk.w;
    }
    #pragma unroll
    for (int o = 16; o; o >>= 1) {
        aq += __shfl_xor_sync(0xffffffffu, aq, o);
        ak += __shfl_xor_sync(0xffffffffu, ak, o);
    }
    if (lane == 0) { g_vq[gw] = aq; g_vk[gw] = ak; }
}

// ---------------- adjacent-pair scores via u and cn: one warp per (b,i) ----------------
__global__ __launch_bounds__(256) void band_dots_kernel(const int* __restrict__ mask) {
    int gw = (blockIdx.x * blockDim.x + threadIdx.x) >> 5;
    int lane = threadIdx.x & 31;
    if (gw >= BS) return;
    int b = gw >> 10;
    int i = gw & (Ss - 1);
    const float* ui = g_u + (size_t)gw * Hh;
    int padi = mask[(b << 10) + i];
    float su = -1e9f, sd = -1e9f;
    float bb = g_bqbk;

    if (i < Ss - 1 && padi && mask[(b << 10) + i + 1]) {
        const float* cj = g_cn + (size_t)(gw + 1) * Hh;
        float acc = 0.f;
        #pragma unroll
        for (int it = 0; it < 8; it++) {
            int c = it * 128 + lane * 4;
            float4 a = *(const float4*)(ui + c);
            float4 v = *(const float4*)(cj + c);
            acc += a.x * v.x + a.y * v.y + a.z * v.z + a.w * v.w;
        }
        #pragma unroll
        for (int o = 16; o; o >>= 1) acc += __shfl_xor_sync(0xffffffffu, acc, o);
        su = (acc + g_vq[gw] + g_vk[gw + 1] + bb) * (1.0f / 32.0f);
    }
    if (i > 0 && padi && mask[(b << 10) + i - 1]) {
        const float* cj = g_cn + (size_t)(gw - 1) * Hh;
        float acc = 0.f;
        #pragma unroll
        for (int it = 0; it < 8; it++) {
            int c = it * 128 + lane * 4;
            float4 a = *(const float4*)(ui + c);
            float4 v = *(const float4*)(cj + c);
            acc += a.x * v.x + a.y * v.y + a.z * v.z + a.w * v.w;
        }
        #pragma unroll
        for (int o = 16; o; o >>= 1) acc += __shfl_xor_sync(0xffffffffu, acc, o);
        sd = (acc + g_vq[gw] + g_vk[gw - 1] + bb) * (1.0f / 32.0f);
    }
    if (lane == 0) { g_sup[gw] = su; g_sdn[gw] = sd; }
}

// ---------------- 2-entry softmax per row ----------------
__global__ void probs_kernel() {
    int idx = blockIdx.x * blockDim.x + threadIdx.x;
    if (idx >= BS) return;
    float su = g_sup[idx], sd = g_sdn[idx];
    float m = fmaxf(su, sd);
    float eu = expf(su - m);
    float ed = expf(sd - m);
    float z = eu + ed;
    g_pup[idx] = eu / z;
    g_pdn[idx] = ed / z;
}

// ---------------- symmetric band values ----------------
__global__ void band_kernel() {
    int idx = blockIdx.x * blockDim.x + threadIdx.x;
    if (idx >= BS) return;
    int i = idx & (Ss - 1);
    if (i < Ss - 1)
        g_band[idx] = sqrtf(g_pup[idx] * g_pdn[idx + 1] + 1e-9f);
}

// ---------------- fused output: one block per (b,row) ----------------
__global__ __launch_bounds__(256) void out_kernel(const float* __restrict__ prior,
                                                  const int* __restrict__ mask,
                                                  float* __restrict__ out,
                                                  int Nout) {
    int row = blockIdx.x;
    int b = row >> 10;
    int r = row & (Ss - 1);
    int tid = threadIdx.x;
    const float c0 = sqrtf(1e-9f);

    float4 p4 = ((const float4*)(prior + (size_t)row * Ss))[tid];
    int4  m4 = ((const int4*)(mask + (b << 10)))[tid];
    int padr = mask[(b << 10) + r];

    float pv[4] = {p4.x, p4.y, p4.z, p4.w};
    int   mc[4] = {m4.x, m4.y, m4.z, m4.w};
    int c_base = tid * 4;

    float nbo[4], graw[4];
    #pragma unroll
    for (int j = 0; j < 4; j++) {
        int c = c_base + j;
        float nbs = c0;
        if (r > 0 && c == r - 1)       nbs = g_band[(b << 10) + r - 1];
        if (r < Ss - 1 && c == r + 1)  nbs = g_band[(b << 10) + r];
        nbo[j]  = pv[j] + (1.0f - pv[j]) * nbs;
        graw[j] = (c == r) ? (2.0f + 1e-9f) : (1.0f + nbo[j]);
    }

    __shared__ float red[8];
    float s = graw[0] + graw[1] + graw[2] + graw[3];
    #pragma unroll
    for (int o = 16; o; o >>= 1) s += __shfl_xor_sync(0xffffffffu, s, o);
    if ((tid & 31) == 0) red[tid >> 5] = s;
    __syncthreads();
    if (tid < 8) {
        float t = red[tid];
        #pragma unroll
        for (int o = 4; o; o >>= 1) t += __shfl_xor_sync(0xffu, t, o);
        if (tid == 0) red[0] = t;
    }
    __syncthreads();
    float invD = 1.0f / (red[0] + 1e-9f);

    float4 go, no;
    float f0 = (padr && mc[0]) ? 1.0f : 0.0f;
    float f1 = (padr && mc[1]) ? 1.0f : 0.0f;
    float f2 = (padr && mc[2]) ? 1.0f : 0.0f;
    float f3 = (padr && mc[3]) ? 1.0f : 0.0f;
    go.x = graw[0] * invD * f0; no.x = nbo[0] * f0;
    go.y = graw[1] * invD * f1; no.y = nbo[1] * f1;
    go.z = graw[2] * invD * f2; no.z = nbo[2] * f2;
    go.w = graw[3] * invD * f3; no.w = nbo[3] * f3;

    size_t base = (size_t)row * Ss + c_base;
    *(float4*)(out + base)                = go;
    *(float4*)(out + (size_t)Nout + base) = no;
}

// ---------------- launch ----------------
extern "C" void kernel_launch(void* const* d_in, const int* in_sizes, int n_in,
                              void* d_out, int out_size) {
    const float* context = (const float*)d_in[0];
    const int*   mask    = (const int*)  d_in[1];
    const float* prior   = (const float*)d_in[2];
    const float* gamma   = (const float*)d_in[3];
    const float* beta    = (const float*)d_in[4];
    const float* Wk      = (const float*)d_in[5];
    const float* bk      = (const float*)d_in[6];
    const float* Wq      = (const float*)d_in[7];
    const float* bq      = (const float*)d_in[8];
    float* out = (float*)d_out;
    int Nout = out_size / 2;

    float *cn, *u, *At;
    cudaGetSymbolAddress((void**)&cn, g_cn);
    cudaGetSymbolAddress((void**)&u,  g_u);
    cudaGetSymbolAddress((void**)&At, g_At);

    static int smem_set = 0;
    if (!smem_set) {
        cudaFuncSetAttribute(gemm_tf32_nt, cudaFuncAttributeMaxDynamicSharedMemorySize, 65536);
        smem_set = 1;
    }

    ln_kernel<<<BS, 256>>>(context, gamma, beta);
    bias_prep<<<257, 256>>>(Wq, bk, Wk, bq);

    // At[e,d] = sum_h Wk[e,h] * Wq[d,h]
    dim3 gsmall(Hh / 128, Hh / 128);
    gemm_tf32_nt<<<gsmall, 256, 65536>>>(Wk, Wq, At, Hh, Hh);

    // u[i,e] = sum_d cn[i,d] * At[e,d]
    dim3 gbig(Hh / 128, BS / 128);
    gemm_tf32_nt<<<gbig, 256, 65536>>>(cn, At, u, Hh, Hh);

    vqvk_kernel<<<(BS * 32) / 256, 256>>>();
    band_dots_kernel<<<(BS * 32) / 256, 256>>>(mask);
    probs_kernel<<<(BS + 255) / 256, 256>>>();
    band_kernel<<<(BS + 255) / 256, 256>>>();

    out_kernel<<<BS, 256>>>(prior, mask, out, Nout);
}

// round 5
// speedup vs baseline: 5.8417x; 1.3860x over previous
#include <cuda_runtime.h>
#include <cuda_bf16.h>
#include <math.h>
#include <stdint.h>

#define Bb 8
#define Ss 1024
#define Hh 1024
#define BS (Bb*Ss)   // 8192

// ---------------- scratch (device globals; no allocation allowed) ----------------
__device__ float          g_cn [(size_t)BS*Hh];   // layernorm output (f32, for band dots)
__device__ __nv_bfloat16  g_cnh[(size_t)BS*Hh];   // layernorm output (bf16, GEMM operand)
__device__ float          g_u  [(size_t)BS*Hh];   // u = cn @ (Wq Wk^T)
__device__ __nv_bfloat16  g_wkh[(size_t)Hh*Hh];
__device__ __nv_bfloat16  g_wqh[(size_t)Hh*Hh];
__device__ __nv_bfloat16  g_Ath[(size_t)Hh*Hh];   // At = Wk @ Wq^T (bf16)
__device__ float g_wqb[Hh];              // Wq @ bk
__device__ float g_wkb[Hh];              // Wk @ bq
__device__ float g_bqbk;
__device__ float g_vq[BS];
__device__ float g_vk[BS];
__device__ float g_sup[BS];
__device__ float g_sdn[BS];
__device__ float g_band[BS];

// ---------------- LayerNorm: one block (256 thr) per row; emits f32 + bf16 ----------------
__global__ __launch_bounds__(256) void ln_kernel(const float* __restrict__ x,
                                                 const float* __restrict__ gamma,
                                                 const float* __restrict__ beta) {
    int row = blockIdx.x;
    int tid = threadIdx.x;
    const float4* xr = (const float4*)(x + (size_t)row * Hh);
    float4 v = xr[tid];

    __shared__ float red[8];
    float s = v.x + v.y + v.z + v.w;
    #pragma unroll
    for (int o = 16; o; o >>= 1) s += __shfl_xor_sync(0xffffffffu, s, o);
    if ((tid & 31) == 0) red[tid >> 5] = s;
    __syncthreads();
    if (tid < 8) {
        float t = red[tid];
        #pragma unroll
        for (int o = 4; o; o >>= 1) t += __shfl_xor_sync(0xffu, t, o);
        if (tid == 0) red[0] = t;
    }
    __syncthreads();
    float mu = red[0] * (1.0f / Hh);
    __syncthreads();
    float dx = v.x - mu, dy = v.y - mu, dz = v.z - mu, dw = v.w - mu;
    float ss = dx*dx + dy*dy + dz*dz + dw*dw;
    #pragma unroll
    for (int o = 16; o; o >>= 1) ss += __shfl_xor_sync(0xffffffffu, ss, o);
    if ((tid & 31) == 0) red[tid >> 5] = ss;
    __syncthreads();
    if (tid < 8) {
        float t = red[tid];
        #pragma unroll
        for (int o = 4; o; o >>= 1) t += __shfl_xor_sync(0xffu, t, o);
        if (tid == 0) red[0] = t;
    }
    __syncthreads();
    float var = red[0] * (1.0f / Hh);
    float rstd = rsqrtf(var + 1e-5f);

    float4 gm = ((const float4*)gamma)[tid];
    float4 bt = ((const float4*)beta)[tid];
    float4 o4;
    o4.x = dx * rstd * gm.x + bt.x;
    o4.y = dy * rstd * gm.y + bt.y;
    o4.z = dz * rstd * gm.z + bt.z;
    o4.w = dw * rstd * gm.w + bt.w;
    ((float4*)(g_cn + (size_t)row * Hh))[tid] = o4;

    __nv_bfloat162* ch = (__nv_bfloat162*)(g_cnh + (size_t)row * Hh);
    ch[2 * tid]     = __floats2bfloat162_rn(o4.x, o4.y);
    ch[2 * tid + 1] = __floats2bfloat162_rn(o4.z, o4.w);
}

// ---------------- weight f32 -> bf16 convert ----------------
__global__ __launch_bounds__(256) void conv_w_kernel(const float* __restrict__ Wk,
                                                     const float* __restrict__ Wq) {
    int idx = blockIdx.x * blockDim.x + threadIdx.x;   // float4 index, 0..(1M/4-1)
    float4 a = ((const float4*)Wk)[idx];
    float4 b = ((const float4*)Wq)[idx];
    ((__nv_bfloat162*)g_wkh)[2 * idx]     = __floats2bfloat162_rn(a.x, a.y);
    ((__nv_bfloat162*)g_wkh)[2 * idx + 1] = __floats2bfloat162_rn(a.z, a.w);
    ((__nv_bfloat162*)g_wqh)[2 * idx]     = __floats2bfloat162_rn(b.x, b.y);
    ((__nv_bfloat162*)g_wqh)[2 * idx + 1] = __floats2bfloat162_rn(b.z, b.w);
}

// ---------------- bf16 tensor-core NT GEMM: C[M,N] = Aop[M,K] * Bop[N,K]^T ----------------
// 128x128 block tile, K-tile 64 (bf16), 8 warps (2x4) of 64x32 warp tiles,
// 3-stage cp.async pipeline, XOR swizzle (conflict-free fragment LDS).

__device__ __forceinline__ void cp16(uint32_t dst, const void* src) {
    asm volatile("cp.async.cg.shared.global [%0], [%1], 16;\n" :: "r"(dst), "l"(src));
}

#define MMA_BF16(d, a, b)                                                     \
    asm volatile("mma.sync.aligned.m16n8k16.row.col.f32.bf16.bf16.f32 "       \
                 "{%0,%1,%2,%3},{%4,%5,%6,%7},{%8,%9},{%0,%1,%2,%3};\n"       \
                 : "+f"(d[0]), "+f"(d[1]), "+f"(d[2]), "+f"(d[3])             \
                 : "r"(a[0]), "r"(a[1]), "r"(a[2]), "r"(a[3]),                \
                   "r"(b[0]), "r"(b[1]))

template<int OUT_BF16>
__global__ __launch_bounds__(256) void gemm_bf16_nt(const __nv_bfloat16* __restrict__ Aop,
                                                    const __nv_bfloat16* __restrict__ Bop,
                                                    void* __restrict__ Cout,
                                                    int N, int K) {
    extern __shared__ uint32_t smemw[];      // per stage: A 4096 words + B 4096 words (32KB)
    const int STAGEW = 8192;                 // words per stage
    int tid = threadIdx.x;
    int lane = tid & 31, warp = tid >> 5;
    int wy = warp >> 2, wx = warp & 3;       // 2 x 4 warp grid

    const __nv_bfloat16* Abase = Aop + (size_t)blockIdx.y * 128 * K;
    const __nv_bfloat16* Bbase = Bop + (size_t)blockIdx.x * 128 * K;

    uint32_t sbase = (uint32_t)__cvta_generic_to_shared(smemw);

    float acc[4][4][4];
    #pragma unroll
    for (int i = 0; i < 4; i++)
        #pragma unroll
        for (int j = 0; j < 4; j++)
            #pragma unroll
            for (int r = 0; r < 4; r++) acc[i][j][r] = 0.f;

    // global->smem mapping: thread handles rows (tid>>3)+32r, 16B chunk (tid&7)
    int mrow = tid >> 3;                     // 0..31
    int c4   = tid & 7;                      // chunk (16B = 8 bf16)
    int c4x  = c4 ^ (mrow & 7);              // xor swizzle on 16B granules
    const __nv_bfloat16* Asrc = Abase + (size_t)mrow * K + 8 * c4;
    const __nv_bfloat16* Bsrc = Bbase + (size_t)mrow * K + 8 * c4;
    uint32_t Adst = sbase + (uint32_t)(mrow * 32 + 4 * c4x) * 4u;
    uint32_t Bdst = Adst + 16384u;
    const uint32_t STAGEB = 32768u;

    int ntiles = K >> 6;                     // K-tile = 64 bf16

    // stage loader
    auto load_stage = [&](int slot, int k0) {
        uint32_t so = (uint32_t)slot * STAGEB;
        #pragma unroll
        for (int r = 0; r < 4; r++) {
            cp16(Adst + so + (uint32_t)r * 4096u, Asrc + (size_t)(32 * r) * K + k0);
            cp16(Bdst + so + (uint32_t)r * 4096u, Bsrc + (size_t)(32 * r) * K + k0);
        }
        asm volatile("cp.async.commit_group;\n");
    };

    load_stage(0, 0);
    load_stage(1, 64);

    int q = lane >> 2, rsel = lane & 3;
    int sw = 4 * q;

    for (int t = 0; t < ntiles; t++) {
        asm volatile("cp.async.wait_group 1;\n");
        __syncthreads();

        int cur = t % 3;
        const uint32_t* sA = smemw + cur * STAGEW;
        const uint32_t* sB = sA + 4096;

        #pragma unroll
        for (int kk = 0; kk < 32; kk += 8) {     // each step = k16
            int col0 = (kk + rsel) ^ sw;
            int col1 = col0 ^ 4;
            uint32_t a[4][4], b[4][2];
            #pragma unroll
            for (int mt = 0; mt < 4; mt++) {
                int m0 = wy * 64 + mt * 16 + q;
                a[mt][0] = sA[m0 * 32 + col0];
                a[mt][1] = sA[(m0 + 8) * 32 + col0];
                a[mt][2] = sA[m0 * 32 + col1];
                a[mt][3] = sA[(m0 + 8) * 32 + col1];
            }
            #pragma unroll
            for (int nt = 0; nt < 4; nt++) {
                int n0 = wx * 32 + nt * 8 + q;
                b[nt][0] = sB[n0 * 32 + col0];
                b[nt][1] = sB[n0 * 32 + col1];
            }
            #pragma unroll
            for (int mt = 0; mt < 4; mt++)
                #pragma unroll
                for (int nt = 0; nt < 4; nt++)
                    MMA_BF16(acc[mt][nt], a[mt], b[nt]);
        }

        __syncthreads();
        if (t + 2 < ntiles) load_stage((t + 2) % 3, (t + 2) * 64);
    }

    // epilogue
    #pragma unroll
    for (int mt = 0; mt < 4; mt++) {
        int r0 = blockIdx.y * 128 + wy * 64 + mt * 16 + (lane >> 2);
        #pragma unroll
        for (int nt = 0; nt < 4; nt++) {
            int cc = blockIdx.x * 128 + wx * 32 + nt * 8 + 2 * (lane & 3);
            if (OUT_BF16) {
                __nv_bfloat16* C = (__nv_bfloat16*)Cout;
                *(__nv_bfloat162*)(C + (size_t)r0 * N + cc) =
                    __floats2bfloat162_rn(acc[mt][nt][0], acc[mt][nt][1]);
                *(__nv_bfloat162*)(C + (size_t)(r0 + 8) * N + cc) =
                    __floats2bfloat162_rn(acc[mt][nt][2], acc[mt][nt][3]);
            } else {
                float* C = (float*)Cout;
                *(float2*)(C + (size_t)r0 * N + cc)       = make_float2(acc[mt][nt][0], acc[mt][nt][1]);
                *(float2*)(C + (size_t)(r0 + 8) * N + cc) = make_float2(acc[mt][nt][2], acc[mt][nt][3]);
            }
        }
    }
}

// ---------------- bias precompute: wqb = Wq@bk, wkb = Wk@bq, bqbk = bq.bk ----------------
__global__ __launch_bounds__(256) void bias_prep(const float* __restrict__ Wq,
                                                 const float* __restrict__ bk,
                                                 const float* __restrict__ Wk,
                                                 const float* __restrict__ bq) {
    int gw = (blockIdx.x * blockDim.x + threadIdx.x) >> 5;
    int lane = threadIdx.x & 31;
    if (gw > 2048) return;
    const float* row; const float* vec;
    if (gw < 1024)      { row = Wq + (size_t)gw * Hh;          vec = bk; }
    else if (gw < 2048) { row = Wk + (size_t)(gw - 1024) * Hh; vec = bq; }
    else                { row = bq;                            vec = bk; }
    float acc = 0.f;
    #pragma unroll
    for (int it = 0; it < 8; it++) {
        int c = it * 128 + lane * 4;
        float4 a = *(const float4*)(row + c);
        float4 v = *(const float4*)(vec + c);
        acc += a.x * v.x + a.y * v.y + a.z * v.z + a.w * v.w;
    }
    #pragma unroll
    for (int o = 16; o; o >>= 1) acc += __shfl_xor_sync(0xffffffffu, acc, o);
    if (lane == 0) {
        if (gw < 1024)      g_wqb[gw] = acc;
        else if (gw < 2048) g_wkb[gw - 1024] = acc;
        else                g_bqbk = acc;
    }
}

// ---------------- vq_i = cn_i . wqb, vk_i = cn_i . wkb (one warp/row) ----------------
__global__ __launch_bounds__(256) void vqvk_kernel() {
    int gw = (blockIdx.x * blockDim.x + threadIdx.x) >> 5;
    int lane = threadIdx.x & 31;
    if (gw >= BS) return;
    const float* cni = g_cn + (size_t)gw * Hh;
    float aq = 0.f, ak = 0.f;
    #pragma unroll
    for (int it = 0; it < 8; it++) {
        int c = it * 128 + lane * 4;
        float4 x  = *(const float4*)(cni + c);
        float4 wq = *(const float4*)(g_wqb + c);
        float4 wk = *(const float4*)(g_wkb + c);
        aq += x.x * wq.x + x.y * wq.y + x.z * wq.z + x.w * wq.w;
        ak += x.x * wk.x + x.y * wk.y + x.z * wk.z + x.w * wk.w;
    }
    #pragma unroll
    for (int o = 16; o; o >>= 1) {
        aq += __shfl_xor_sync(0xffffffffu, aq, o);
        ak += __shfl_xor_sync(0xffffffffu, ak, o);
    }
    if (lane == 0) { g_vq[gw] = aq; g_vk[gw] = ak; }
}

// ---------------- adjacent-pair scores via u and cn: one warp per (b,i) ----------------
__global__ __launch_bounds__(256) void band_dots_kernel(const int* __restrict__ mask) {
    int gw = (blockIdx.x * blockDim.x + threadIdx.x) >> 5;
    int lane = threadIdx.x & 31;
    if (gw >= BS) return;
    int b = gw >> 10;
    int i = gw & (Ss - 1);
    const float* ui = g_u + (size_t)gw * Hh;
    int padi = mask[(b << 10) + i];
    float su = -1e9f, sd = -1e9f;
    float bb = g_bqbk;

    if (i < Ss - 1 && padi && mask[(b << 10) + i + 1]) {
        const float* cj = g_cn + (size_t)(gw + 1) * Hh;
        float acc = 0.f;
        #pragma unroll
        for (int it = 0; it < 8; it++) {
            int c = it * 128 + lane * 4;
            float4 a = *(const float4*)(ui + c);
            float4 v = *(const float4*)(cj + c);
            acc += a.x * v.x + a.y * v.y + a.z * v.z + a.w * v.w;
        }
        #pragma unroll
        for (int o = 16; o; o >>= 1) acc += __shfl_xor_sync(0xffffffffu, acc, o);
        su = (acc + g_vq[gw] + g_vk[gw + 1] + bb) * (1.0f / 32.0f);
    }
    if (i > 0 && padi && mask[(b << 10) + i - 1]) {
        const float* cj = g_cn + (size_t)(gw - 1) * Hh;
        float acc = 0.f;
        #pragma unroll
        for (int it = 0; it < 8; it++) {
            int c = it * 128 + lane * 4;
            float4 a = *(const float4*)(ui + c);
            float4 v = *(const float4*)(cj + c);
            acc += a.x * v.x + a.y * v.y + a.z * v.z + a.w * v.w;
        }
        #pragma unroll
        for (int o = 16; o; o >>= 1) acc += __shfl_xor_sync(0xffffffffu, acc, o);
        sd = (acc + g_vq[gw] + g_vk[gw - 1] + bb) * (1.0f / 32.0f);
    }
    if (lane == 0) { g_sup[gw] = su; g_sdn[gw] = sd; }
}

// ---------------- fused 2-entry softmax + symmetric band ----------------
__global__ void band_kernel() {
    int idx = blockIdx.x * blockDim.x + threadIdx.x;
    if (idx >= BS) return;
    int i = idx & (Ss - 1);
    if (i >= Ss - 1) return;
    // pup(i)
    float su = g_sup[idx], sd = g_sdn[idx];
    float m = fmaxf(su, sd);
    float eu = expf(su - m), ed = expf(sd - m);
    float pup = eu / (eu + ed);
    // pdn(i+1)
    float su2 = g_sup[idx + 1], sd2 = g_sdn[idx + 1];
    float m2 = fmaxf(su2, sd2);
    float eu2 = expf(su2 - m2), ed2 = expf(sd2 - m2);
    float pdn = ed2 / (eu2 + ed2);
    g_band[idx] = sqrtf(pup * pdn + 1e-9f);
}

// ---------------- fused output: one block per (b,row) ----------------
__global__ __launch_bounds__(256) void out_kernel(const float* __restrict__ prior,
                                                  const int* __restrict__ mask,
                                                  float* __restrict__ out,
                                                  int Nout) {
    int row = blockIdx.x;
    int b = row >> 10;
    int r = row & (Ss - 1);
    int tid = threadIdx.x;
    const float c0 = sqrtf(1e-9f);

    float4 p4 = ((const float4*)(prior + (size_t)row * Ss))[tid];
    int4  m4 = ((const int4*)(mask + (b << 10)))[tid];
    int padr = mask[(b << 10) + r];

    float pv[4] = {p4.x, p4.y, p4.z, p4.w};
    int   mc[4] = {m4.x, m4.y, m4.z, m4.w};
    int c_base = tid * 4;

    float nbo[4], graw[4];
    #pragma unroll
    for (int j = 0; j < 4; j++) {
        int c = c_base + j;
        float nbs = c0;
        if (r > 0 && c == r - 1)       nbs = g_band[(b << 10) + r - 1];
        if (r < Ss - 1 && c == r + 1)  nbs = g_band[(b << 10) + r];
        nbo[j]  = pv[j] + (1.0f - pv[j]) * nbs;
        graw[j] = (c == r) ? (2.0f + 1e-9f) : (1.0f + nbo[j]);
    }

    __shared__ float red[8];
    float s = graw[0] + graw[1] + graw[2] + graw[3];
    #pragma unroll
    for (int o = 16; o; o >>= 1) s += __shfl_xor_sync(0xffffffffu, s, o);
    if ((tid & 31) == 0) red[tid >> 5] = s;
    __syncthreads();
    if (tid < 8) {
        float t = red[tid];
        #pragma unroll
        for (int o = 4; o; o >>= 1) t += __shfl_xor_sync(0xffu, t, o);
        if (tid == 0) red[0] = t;
    }
    __syncthreads();
    float invD = 1.0f / (red[0] + 1e-9f);

    float4 go, no;
    float f0 = (padr && mc[0]) ? 1.0f : 0.0f;
    float f1 = (padr && mc[1]) ? 1.0f : 0.0f;
    float f2 = (padr && mc[2]) ? 1.0f : 0.0f;
    float f3 = (padr && mc[3]) ? 1.0f : 0.0f;
    go.x = graw[0] * invD * f0; no.x = nbo[0] * f0;
    go.y = graw[1] * invD * f1; no.y = nbo[1] * f1;
    go.z = graw[2] * invD * f2; no.z = nbo[2] * f2;
    go.w = graw[3] * invD * f3; no.w = nbo[3] * f3;

    size_t base = (size_t)row * Ss + c_base;
    *(float4*)(out + base)                = go;
    *(float4*)(out + (size_t)Nout + base) = no;
}

// ---------------- launch ----------------
extern "C" void kernel_launch(void* const* d_in, const int* in_sizes, int n_in,
                              void* d_out, int out_size) {
    const float* context = (const float*)d_in[0];
    const int*   mask    = (const int*)  d_in[1];
    const float* prior   = (const float*)d_in[2];
    const float* gamma   = (const float*)d_in[3];
    const float* beta    = (const float*)d_in[4];
    const float* Wk      = (const float*)d_in[5];
    const float* bk      = (const float*)d_in[6];
    const float* Wq      = (const float*)d_in[7];
    const float* bq      = (const float*)d_in[8];
    float* out = (float*)d_out;
    int Nout = out_size / 2;

    __nv_bfloat16 *cnh, *wkh, *wqh, *Ath;
    float *u;
    cudaGetSymbolAddress((void**)&cnh, g_cnh);
    cudaGetSymbolAddress((void**)&wkh, g_wkh);
    cudaGetSymbolAddress((void**)&wqh, g_wqh);
    cudaGetSymbolAddress((void**)&Ath, g_Ath);
    cudaGetSymbolAddress((void**)&u,   g_u);

    static int smem_set = 0;
    if (!smem_set) {
        cudaFuncSetAttribute(gemm_bf16_nt<0>, cudaFuncAttributeMaxDynamicSharedMemorySize, 98304);
        cudaFuncSetAttribute(gemm_bf16_nt<1>, cudaFuncAttributeMaxDynamicSharedMemorySize, 98304);
        smem_set = 1;
    }

    ln_kernel<<<BS, 256>>>(context, gamma, beta);
    conv_w_kernel<<<(Hh * Hh / 4) / 256, 256>>>(Wk, Wq);
    bias_prep<<<257, 256>>>(Wq, bk, Wk, bq);

    // At[e,d] = sum_h Wk[e,h] * Wq[d,h]   (bf16 out)
    dim3 gsmall(Hh / 128, Hh / 128);
    gemm_bf16_nt<1><<<gsmall, 256, 98304>>>(wkh, wqh, Ath, Hh, Hh);

    // u[i,e] = sum_d cn[i,d] * At[e,d]    (f32 out)
    dim3 gbig(Hh / 128, BS / 128);
    gemm_bf16_nt<0><<<gbig, 256, 98304>>>(cnh, Ath, u, Hh, Hh);

    vqvk_kernel<<<(BS * 32) / 256, 256>>>();
    band_dots_kernel<<<(BS * 32) / 256, 256>>>(mask);
    band_kernel<<<(BS + 255) / 256, 256>>>();

    out_kernel<<<BS, 256>>>(prior, mask, out, Nout);
}

// round 6
// speedup vs baseline: 6.0948x; 1.0433x over previous
#include <cuda_runtime.h>
#include <cuda_bf16.h>
#include <math.h>
#include <stdint.h>

#define Bb 8
#define Ss 1024
#define Hh 1024
#define BS (Bb*Ss)   // 8192

// ---------------- scratch (device globals; no allocation allowed) ----------------
__device__ __nv_bfloat16  g_cnh[(size_t)BS*Hh];   // layernorm output (bf16)
__device__ __nv_bfloat16  g_uh [(size_t)BS*Hh];   // u = cn @ (Wq Wk^T)  (bf16)
__device__ __nv_bfloat16  g_wkh[(size_t)Hh*Hh];
__device__ __nv_bfloat16  g_wqh[(size_t)Hh*Hh];
__device__ __nv_bfloat16  g_Ath[(size_t)Hh*Hh];   // At = Wk @ Wq^T (bf16)
__device__ float g_wqb[Hh];              // Wq @ bk
__device__ float g_wkb[Hh];              // Wk @ bq
__device__ float g_bqbk;
__device__ float g_vq[BS];
__device__ float g_vk[BS];
__device__ float g_sup[BS];
__device__ float g_sdn[BS];
__device__ float g_band[BS];

// ---------------- LayerNorm: one block (256 thr) per row; emits bf16 ----------------
__global__ __launch_bounds__(256) void ln_kernel(const float* __restrict__ x,
                                                 const float* __restrict__ gamma,
                                                 const float* __restrict__ beta) {
    int row = blockIdx.x;
    int tid = threadIdx.x;
    const float4* xr = (const float4*)(x + (size_t)row * Hh);
    float4 v = xr[tid];

    __shared__ float red[8];
    float s = v.x + v.y + v.z + v.w;
    #pragma unroll
    for (int o = 16; o; o >>= 1) s += __shfl_xor_sync(0xffffffffu, s, o);
    if ((tid & 31) == 0) red[tid >> 5] = s;
    __syncthreads();
    if (tid < 8) {
        float t = red[tid];
        #pragma unroll
        for (int o = 4; o; o >>= 1) t += __shfl_xor_sync(0xffu, t, o);
        if (tid == 0) red[0] = t;
    }
    __syncthreads();
    float mu = red[0] * (1.0f / Hh);
    __syncthreads();
    float dx = v.x - mu, dy = v.y - mu, dz = v.z - mu, dw = v.w - mu;
    float ss = dx*dx + dy*dy + dz*dz + dw*dw;
    #pragma unroll
    for (int o = 16; o; o >>= 1) ss += __shfl_xor_sync(0xffffffffu, ss, o);
    if ((tid & 31) == 0) red[tid >> 5] = ss;
    __syncthreads();
    if (tid < 8) {
        float t = red[tid];
        #pragma unroll
        for (int o = 4; o; o >>= 1) t += __shfl_xor_sync(0xffu, t, o);
        if (tid == 0) red[0] = t;
    }
    __syncthreads();
    float var = red[0] * (1.0f / Hh);
    float rstd = rsqrtf(var + 1e-5f);

    float4 gm = ((const float4*)gamma)[tid];
    float4 bt = ((const float4*)beta)[tid];
    float ox = dx * rstd * gm.x + bt.x;
    float oy = dy * rstd * gm.y + bt.y;
    float oz = dz * rstd * gm.z + bt.z;
    float ow = dw * rstd * gm.w + bt.w;

    __nv_bfloat162* ch = (__nv_bfloat162*)(g_cnh + (size_t)row * Hh);
    ch[2 * tid]     = __floats2bfloat162_rn(ox, oy);
    ch[2 * tid + 1] = __floats2bfloat162_rn(oz, ow);
}

// ---------------- fused weight convert + bias dots ----------------
// gw<1024: Wq row -> g_wqh, dot bk -> g_wqb ; gw in [1024,2048): Wk row -> g_wkh, dot bq -> g_wkb
// gw==2048: bqbk = bq.bk
__global__ __launch_bounds__(256) void convbias_kernel(const float* __restrict__ Wq,
                                                       const float* __restrict__ bk,
                                                       const float* __restrict__ Wk,
                                                       const float* __restrict__ bq) {
    int gw = (blockIdx.x * blockDim.x + threadIdx.x) >> 5;
    int lane = threadIdx.x & 31;
    if (gw > 2048) return;

    if (gw == 2048) {
        float acc = 0.f;
        #pragma unroll
        for (int it = 0; it < 8; it++) {
            int c = it * 128 + lane * 4;
            float4 a = *(const float4*)(bq + c);
            float4 v = *(const float4*)(bk + c);
            acc += a.x * v.x + a.y * v.y + a.z * v.z + a.w * v.w;
        }
        #pragma unroll
        for (int o = 16; o; o >>= 1) acc += __shfl_xor_sync(0xffffffffu, acc, o);
        if (lane == 0) g_bqbk = acc;
        return;
    }

    const float* row; const float* vec; __nv_bfloat16* dsth;
    int r;
    if (gw < 1024) { r = gw;        row = Wq + (size_t)r * Hh; vec = bk; dsth = g_wqh + (size_t)r * Hh; }
    else           { r = gw - 1024; row = Wk + (size_t)r * Hh; vec = bq; dsth = g_wkh + (size_t)r * Hh; }

    float acc = 0.f;
    #pragma unroll
    for (int it = 0; it < 8; it++) {
        int c = it * 128 + lane * 4;
        float4 a = *(const float4*)(row + c);
        float4 v = *(const float4*)(vec + c);
        acc += a.x * v.x + a.y * v.y + a.z * v.z + a.w * v.w;
        __nv_bfloat162* d2 = (__nv_bfloat162*)(dsth + c);
        d2[0] = __floats2bfloat162_rn(a.x, a.y);
        d2[1] = __floats2bfloat162_rn(a.z, a.w);
    }
    #pragma unroll
    for (int o = 16; o; o >>= 1) acc += __shfl_xor_sync(0xffffffffu, acc, o);
    if (lane == 0) {
        if (gw < 1024) g_wqb[r] = acc;
        else           g_wkb[r] = acc;
    }
}

// ---------------- common MMA helpers ----------------
__device__ __forceinline__ void cp16(uint32_t dst, const void* src) {
    asm volatile("cp.async.cg.shared.global [%0], [%1], 16;\n" :: "r"(dst), "l"(src));
}

#define MMA_BF16(d, a, b)                                                     \
    asm volatile("mma.sync.aligned.m16n8k16.row.col.f32.bf16.bf16.f32 "       \
                 "{%0,%1,%2,%3},{%4,%5,%6,%7},{%8,%9},{%0,%1,%2,%3};\n"       \
                 : "+f"(d[0]), "+f"(d[1]), "+f"(d[2]), "+f"(d[3])             \
                 : "r"(a[0]), "r"(a[1]), "r"(a[2]), "r"(a[3]),                \
                   "r"(b[0]), "r"(b[1]))

// ---------------- bf16 NT GEMM, 128x128 tile, 8 warps, 3-stage; bf16 out ----------------
__global__ __launch_bounds__(256) void gemm_bf16_nt(const __nv_bfloat16* __restrict__ Aop,
                                                    const __nv_bfloat16* __restrict__ Bop,
                                                    __nv_bfloat16* __restrict__ C,
                                                    int N, int K) {
    extern __shared__ uint32_t smemw[];
    const int STAGEW = 8192;
    int tid = threadIdx.x;
    int lane = tid & 31, warp = tid >> 5;
    int wy = warp >> 2, wx = warp & 3;

    const __nv_bfloat16* Abase = Aop + (size_t)blockIdx.y * 128 * K;
    const __nv_bfloat16* Bbase = Bop + (size_t)blockIdx.x * 128 * K;

    uint32_t sbase = (uint32_t)__cvta_generic_to_shared(smemw);

    float acc[4][4][4];
    #pragma unroll
    for (int i = 0; i < 4; i++)
        #pragma unroll
        for (int j = 0; j < 4; j++)
            #pragma unroll
            for (int r = 0; r < 4; r++) acc[i][j][r] = 0.f;

    int mrow = tid >> 3;
    int c4   = tid & 7;
    int c4x  = c4 ^ (mrow & 7);
    const __nv_bfloat16* Asrc = Abase + (size_t)mrow * K + 8 * c4;
    const __nv_bfloat16* Bsrc = Bbase + (size_t)mrow * K + 8 * c4;
    uint32_t Adst = sbase + (uint32_t)(mrow * 32 + 4 * c4x) * 4u;
    uint32_t Bdst = Adst + 16384u;
    const uint32_t STAGEB = 32768u;

    int ntiles = K >> 6;

    auto load_stage = [&](int slot, int k0) {
        uint32_t so = (uint32_t)slot * STAGEB;
        #pragma unroll
        for (int r = 0; r < 4; r++) {
            cp16(Adst + so + (uint32_t)r * 4096u, Asrc + (size_t)(32 * r) * K + k0);
            cp16(Bdst + so + (uint32_t)r * 4096u, Bsrc + (size_t)(32 * r) * K + k0);
        }
        asm volatile("cp.async.commit_group;\n");
    };

    load_stage(0, 0);
    load_stage(1, 64);

    int q = lane >> 2, rsel = lane & 3;
    int sw = 4 * q;

    for (int t = 0; t < ntiles; t++) {
        asm volatile("cp.async.wait_group 1;\n");
        __syncthreads();

        int cur = t % 3;
        const uint32_t* sA = smemw + cur * STAGEW;
        const uint32_t* sB = sA + 4096;

        #pragma unroll
        for (int kk = 0; kk < 32; kk += 8) {
            int col0 = (kk + rsel) ^ sw;
            int col1 = col0 ^ 4;
            uint32_t a[4][4], b[4][2];
            #pragma unroll
            for (int mt = 0; mt < 4; mt++) {
                int m0 = wy * 64 + mt * 16 + q;
                a[mt][0] = sA[m0 * 32 + col0];
                a[mt][1] = sA[(m0 + 8) * 32 + col0];
                a[mt][2] = sA[m0 * 32 + col1];
                a[mt][3] = sA[(m0 + 8) * 32 + col1];
            }
            #pragma unroll
            for (int nt = 0; nt < 4; nt++) {
                int n0 = wx * 32 + nt * 8 + q;
                b[nt][0] = sB[n0 * 32 + col0];
                b[nt][1] = sB[n0 * 32 + col1];
            }
            #pragma unroll
            for (int mt = 0; mt < 4; mt++)
                #pragma unroll
                for (int nt = 0; nt < 4; nt++)
                    MMA_BF16(acc[mt][nt], a[mt], b[nt]);
        }

        __syncthreads();
        if (t + 2 < ntiles) load_stage((t + 2) % 3, (t + 2) * 64);
    }

    #pragma unroll
    for (int mt = 0; mt < 4; mt++) {
        int r0 = blockIdx.y * 128 + wy * 64 + mt * 16 + (lane >> 2);
        #pragma unroll
        for (int nt = 0; nt < 4; nt++) {
            int cc = blockIdx.x * 128 + wx * 32 + nt * 8 + 2 * (lane & 3);
            *(__nv_bfloat162*)(C + (size_t)r0 * N + cc) =
                __floats2bfloat162_rn(acc[mt][nt][0], acc[mt][nt][1]);
            *(__nv_bfloat162*)(C + (size_t)(r0 + 8) * N + cc) =
                __floats2bfloat162_rn(acc[mt][nt][2], acc[mt][nt][3]);
        }
    }
}

// ---------------- bf16 NT GEMM, 64x64 tile, 4 warps (2x2 of 32x32), 3-stage; bf16 out ----------------
__global__ __launch_bounds__(128) void gemm_bf16_nt64(const __nv_bfloat16* __restrict__ Aop,
                                                      const __nv_bfloat16* __restrict__ Bop,
                                                      __nv_bfloat16* __restrict__ C,
                                                      int N, int K) {
    extern __shared__ uint32_t smemw[];
    const int STAGEW = 4096;                 // A 2048 + B 2048 words
    int tid = threadIdx.x;
    int lane = tid & 31, warp = tid >> 5;
    int wy = warp >> 1, wx = warp & 1;       // 2x2 warps

    const __nv_bfloat16* Abase = Aop + (size_t)blockIdx.y * 64 * K;
    const __nv_bfloat16* Bbase = Bop + (size_t)blockIdx.x * 64 * K;

    uint32_t sbase = (uint32_t)__cvta_generic_to_shared(smemw);

    float acc[2][4][4];
    #pragma unroll
    for (int i = 0; i < 2; i++)
        #pragma unroll
        for (int j = 0; j < 4; j++)
            #pragma unroll
            for (int r = 0; r < 4; r++) acc[i][j][r] = 0.f;

    int mrow = tid >> 3;                     // 0..15
    int c4   = tid & 7;
    int c4x  = c4 ^ (mrow & 7);
    const __nv_bfloat16* Asrc = Abase + (size_t)mrow * K + 8 * c4;
    const __nv_bfloat16* Bsrc = Bbase + (size_t)mrow * K + 8 * c4;
    uint32_t Adst = sbase + (uint32_t)(mrow * 32 + 4 * c4x) * 4u;
    uint32_t Bdst = Adst + 8192u;            // A region 2048 words
    const uint32_t STAGEB = 16384u;

    int ntiles = K >> 6;

    auto load_stage = [&](int slot, int k0) {
        uint32_t so = (uint32_t)slot * STAGEB;
        #pragma unroll
        for (int r = 0; r < 4; r++) {        // rows 16 apart -> 64 rows
            cp16(Adst + so + (uint32_t)r * 2048u, Asrc + (size_t)(16 * r) * K + k0);
            cp16(Bdst + so + (uint32_t)r * 2048u, Bsrc + (size_t)(16 * r) * K + k0);
        }
        asm volatile("cp.async.commit_group;\n");
    };

    load_stage(0, 0);
    load_stage(1, 64);

    int q = lane >> 2, rsel = lane & 3;
    int sw = 4 * q;

    for (int t = 0; t < ntiles; t++) {
        asm volatile("cp.async.wait_group 1;\n");
        __syncthreads();

        int cur = t % 3;
        const uint32_t* sA = smemw + cur * STAGEW;
        const uint32_t* sB = sA + 2048;

        #pragma unroll
        for (int kk = 0; kk < 32; kk += 8) {
            int col0 = (kk + rsel) ^ sw;
            int col1 = col0 ^ 4;
            uint32_t a[2][4], b[4][2];
            #pragma unroll
            for (int mt = 0; mt < 2; mt++) {
                int m0 = wy * 32 + mt * 16 + q;
                a[mt][0] = sA[m0 * 32 + col0];
                a[mt][1] = sA[(m0 + 8) * 32 + col0];
                a[mt][2] = sA[m0 * 32 + col1];
                a[mt][3] = sA[(m0 + 8) * 32 + col1];
            }
            #pragma unroll
            for (int nt = 0; nt < 4; nt++) {
                int n0 = wx * 32 + nt * 8 + q;
                b[nt][0] = sB[n0 * 32 + col0];
                b[nt][1] = sB[n0 * 32 + col1];
            }
            #pragma unroll
            for (int mt = 0; mt < 2; mt++)
                #pragma unroll
                for (int nt = 0; nt < 4; nt++)
                    MMA_BF16(acc[mt][nt], a[mt], b[nt]);
        }

        __syncthreads();
        if (t + 2 < ntiles) load_stage((t + 2) % 3, (t + 2) * 64);
    }

    #pragma unroll
    for (int mt = 0; mt < 2; mt++) {
        int r0 = blockIdx.y * 64 + wy * 32 + mt * 16 + (lane >> 2);
        #pragma unroll
        for (int nt = 0; nt < 4; nt++) {
            int cc = blockIdx.x * 64 + wx * 32 + nt * 8 + 2 * (lane & 3);
            *(__nv_bfloat162*)(C + (size_t)r0 * N + cc) =
                __floats2bfloat162_rn(acc[mt][nt][0], acc[mt][nt][1]);
            *(__nv_bfloat162*)(C + (size_t)(r0 + 8) * N + cc) =
                __floats2bfloat162_rn(acc[mt][nt][2], acc[mt][nt][3]);
        }
    }
}

// ---------------- bf16 dot helper: 1024 elems across a warp ----------------
__device__ __forceinline__ float warp_dot_bf16(const __nv_bfloat16* __restrict__ a,
                                               const __nv_bfloat16* __restrict__ b,
                                               int lane) {
    float acc = 0.f;
    #pragma unroll
    for (int it = 0; it < 4; it++) {
        int c = it * 256 + lane * 8;
        uint4 aw = *(const uint4*)(a + c);
        uint4 bw = *(const uint4*)(b + c);
        const __nv_bfloat162* a2 = (const __nv_bfloat162*)&aw;
        const __nv_bfloat162* b2 = (const __nv_bfloat162*)&bw;
        #pragma unroll
        for (int j = 0; j < 4; j++) {
            float2 fa = __bfloat1622float2(a2[j]);
            float2 fb = __bfloat1622float2(b2[j]);
            acc += fa.x * fb.x + fa.y * fb.y;
        }
    }
    #pragma unroll
    for (int o = 16; o; o >>= 1) acc += __shfl_xor_sync(0xffffffffu, acc, o);
    return acc;
}

// ---------------- vq_i = cn_i . wqb, vk_i = cn_i . wkb (one warp/row, bf16 cn) ----------------
__global__ __launch_bounds__(256) void vqvk_kernel() {
    int gw = (blockIdx.x * blockDim.x + threadIdx.x) >> 5;
    int lane = threadIdx.x & 31;
    if (gw >= BS) return;
    const __nv_bfloat16* cni = g_cnh + (size_t)gw * Hh;
    float aq = 0.f, ak = 0.f;
    #pragma unroll
    for (int it = 0; it < 4; it++) {
        int c = it * 256 + lane * 8;
        uint4 xw = *(const uint4*)(cni + c);
        const __nv_bfloat162* x2 = (const __nv_bfloat162*)&xw;
        #pragma unroll
        for (int j = 0; j < 4; j++) {
            float2 fx = __bfloat1622float2(x2[j]);
            int cc = c + 2 * j;
            aq += fx.x * g_wqb[cc] + fx.y * g_wqb[cc + 1];
            ak += fx.x * g_wkb[cc] + fx.y * g_wkb[cc + 1];
        }
    }
    #pragma unroll
    for (int o = 16; o; o >>= 1) {
        aq += __shfl_xor_sync(0xffffffffu, aq, o);
        ak += __shfl_xor_sync(0xffffffffu, ak, o);
    }
    if (lane == 0) { g_vq[gw] = aq; g_vk[gw] = ak; }
}

// ---------------- adjacent-pair scores via u and cn (bf16): one warp per (b,i) ----------------
__global__ __launch_bounds__(256) void band_dots_kernel(const int* __restrict__ mask) {
    int gw = (blockIdx.x * blockDim.x + threadIdx.x) >> 5;
    int lane = threadIdx.x & 31;
    if (gw >= BS) return;
    int b = gw >> 10;
    int i = gw & (Ss - 1);
    const __nv_bfloat16* ui = g_uh + (size_t)gw * Hh;
    int padi = mask[(b << 10) + i];
    float su = -1e9f, sd = -1e9f;
    float bb = g_bqbk;

    if (i < Ss - 1 && padi && mask[(b << 10) + i + 1]) {
        float acc = warp_dot_bf16(ui, g_cnh + (size_t)(gw + 1) * Hh, lane);
        su = (acc + g_vq[gw] + g_vk[gw + 1] + bb) * (1.0f / 32.0f);
    }
    if (i > 0 && padi && mask[(b << 10) + i - 1]) {
        float acc = warp_dot_bf16(ui, g_cnh + (size_t)(gw - 1) * Hh, lane);
        sd = (acc + g_vq[gw] + g_vk[gw - 1] + bb) * (1.0f / 32.0f);
    }
    if (lane == 0) { g_sup[gw] = su; g_sdn[gw] = sd; }
}

// ---------------- fused 2-entry softmax + symmetric band ----------------
__global__ void band_kernel() {
    int idx = blockIdx.x * blockDim.x + threadIdx.x;
    if (idx >= BS) return;
    int i = idx & (Ss - 1);
    if (i >= Ss - 1) return;
    float su = g_sup[idx], sd = g_sdn[idx];
    float m = fmaxf(su, sd);
    float eu = expf(su - m), ed = expf(sd - m);
    float pup = eu / (eu + ed);
    float su2 = g_sup[idx + 1], sd2 = g_sdn[idx + 1];
    float m2 = fmaxf(su2, sd2);
    float eu2 = expf(su2 - m2), ed2 = expf(sd2 - m2);
    float pdn = ed2 / (eu2 + ed2);
    g_band[idx] = sqrtf(pup * pdn + 1e-9f);
}

// ---------------- fused output: one block per (b,row) ----------------
__global__ __launch_bounds__(256) void out_kernel(const float* __restrict__ prior,
                                                  const int* __restrict__ mask,
                                                  float* __restrict__ out,
                                                  int Nout) {
    int row = blockIdx.x;
    int b = row >> 10;
    int r = row & (Ss - 1);
    int tid = threadIdx.x;
    const float c0 = sqrtf(1e-9f);

    float4 p4 = ((const float4*)(prior + (size_t)row * Ss))[tid];
    int4  m4 = ((const int4*)(mask + (b << 10)))[tid];
    int padr = mask[(b << 10) + r];

    float pv[4] = {p4.x, p4.y, p4.z, p4.w};
    int   mc[4] = {m4.x, m4.y, m4.z, m4.w};
    int c_base = tid * 4;

    float nbo[4], graw[4];
    #pragma unroll
    for (int j = 0; j < 4; j++) {
        int c = c_base + j;
        float nbs = c0;
        if (r > 0 && c == r - 1)       nbs = g_band[(b << 10) + r - 1];
        if (r < Ss - 1 && c == r + 1)  nbs = g_band[(b << 10) + r];
        nbo[j]  = pv[j] + (1.0f - pv[j]) * nbs;
        graw[j] = (c == r) ? (2.0f + 1e-9f) : (1.0f + nbo[j]);
    }

    __shared__ float red[8];
    float s = graw[0] + graw[1] + graw[2] + graw[3];
    #pragma unroll
    for (int o = 16; o; o >>= 1) s += __shfl_xor_sync(0xffffffffu, s, o);
    if ((tid & 31) == 0) red[tid >> 5] = s;
    __syncthreads();
    if (tid < 8) {
        float t = red[tid];
        #pragma unroll
        for (int o = 4; o; o >>= 1) t += __shfl_xor_sync(0xffu, t, o);
        if (tid == 0) red[0] = t;
    }
    __syncthreads();
    float invD = 1.0f / (red[0] + 1e-9f);

    float4 go, no;
    float f0 = (padr && mc[0]) ? 1.0f : 0.0f;
    float f1 = (padr && mc[1]) ? 1.0f : 0.0f;
    float f2 = (padr && mc[2]) ? 1.0f : 0.0f;
    float f3 = (padr && mc[3]) ? 1.0f : 0.0f;
    go.x = graw[0] * invD * f0; no.x = nbo[0] * f0;
    go.y = graw[1] * invD * f1; no.y = nbo[1] * f1;
    go.z = graw[2] * invD * f2; no.z = nbo[2] * f2;
    go.w = graw[3] * invD * f3; no.w = nbo[3] * f3;

    size_t base = (size_t)row * Ss + c_base;
    *(float4*)(out + base)                = go;
    *(float4*)(out + (size_t)Nout + base) = no;
}

// ---------------- launch ----------------
extern "C" void kernel_launch(void* const* d_in, const int* in_sizes, int n_in,
                              void* d_out, int out_size) {
    const float* context = (const float*)d_in[0];
    const int*   mask    = (const int*)  d_in[1];
    const float* prior   = (const float*)d_in[2];
    const float* gamma   = (const float*)d_in[3];
    const float* beta    = (const float*)d_in[4];
    const float* Wk      = (const float*)d_in[5];
    const float* bk      = (const float*)d_in[6];
    const float* Wq      = (const float*)d_in[7];
    const float* bq      = (const float*)d_in[8];
    float* out = (float*)d_out;
    int Nout = out_size / 2;

    __nv_bfloat16 *cnh, *wkh, *wqh, *Ath, *uh;
    cudaGetSymbolAddress((void**)&cnh, g_cnh);
    cudaGetSymbolAddress((void**)&wkh, g_wkh);
    cudaGetSymbolAddress((void**)&wqh, g_wqh);
    cudaGetSymbolAddress((void**)&Ath, g_Ath);
    cudaGetSymbolAddress((void**)&uh,  g_uh);

    static int smem_set = 0;
    if (!smem_set) {
        cudaFuncSetAttribute(gemm_bf16_nt,   cudaFuncAttributeMaxDynamicSharedMemorySize, 98304);
        cudaFuncSetAttribute(gemm_bf16_nt64, cudaFuncAttributeMaxDynamicSharedMemorySize, 49152);
        smem_set = 1;
    }

    ln_kernel<<<BS, 256>>>(context, gamma, beta);
    convbias_kernel<<<257, 256>>>(Wq, bk, Wk, bq);

    // At[e,d] = sum_h Wk[e,h] * Wq[d,h]   (bf16 out, 64x64 tiles -> 256 CTAs)
    dim3 gsmall(Hh / 64, Hh / 64);
    gemm_bf16_nt64<<<gsmall, 128, 49152>>>(wkh, wqh, Ath, Hh, Hh);

    // u[i,e] = sum_d cn[i,d] * At[e,d]    (bf16 out)
    dim3 gbig(Hh / 128, BS / 128);
    gemm_bf16_nt<<<gbig, 256, 98304>>>(cnh, Ath, uh, Hh, Hh);

    vqvk_kernel<<<(BS * 32) / 256, 256>>>();
    band_dots_kernel<<<(BS * 32) / 256, 256>>>(mask);
    band_kernel<<<(BS + 255) / 256, 256>>>();

    out_kernel<<<BS, 256>>>(prior, mask, out, Nout);
}

// round 11
// speedup vs baseline: 6.4560x; 1.0593x over previous
#include <cuda_runtime.h>
#include <cuda_bf16.h>
#include <math.h>
#include <stdint.h>

#define Bb 8
#define Ss 1024
#define Hh 1024
#define BS (Bb*Ss)   // 8192

// ---------------- scratch (device globals; no allocation allowed) ----------------
__device__ __nv_bfloat16  g_cnh[(size_t)BS*Hh];   // layernorm output (bf16)
__device__ __nv_bfloat16  g_uh [(size_t)BS*Hh];   // u = cn @ (Wq Wk^T)  (bf16)
__device__ __nv_bfloat16  g_wkh[(size_t)Hh*Hh];
__device__ __nv_bfloat16  g_wqh[(size_t)Hh*Hh];
__device__ __nv_bfloat16  g_Ath[(size_t)Hh*Hh];   // At = Wk @ Wq^T (bf16)
__device__ float g_wqb[Hh];              // Wq @ bk
__device__ float g_wkb[Hh];              // Wk @ bq
__device__ float g_bqbk;
__device__ float g_vq[BS];
__device__ float g_vk[BS];
__device__ float g_sup[BS];
__device__ float g_sdn[BS];
__device__ float g_band[BS];

// ================= helpers =================
__device__ __forceinline__ uint32_t smem_u32(const void* p) {
    uint32_t a;
    asm("{ .reg .u64 t; cvta.to.shared.u64 t, %1; cvt.u32.u64 %0, t; }" : "=r"(a) : "l"(p));
    return a;
}
__device__ __forceinline__ void cp16(uint32_t dst, const void* src) {
    asm volatile("cp.async.cg.shared.global [%0], [%1], 16;\n" :: "r"(dst), "l"(src));
}
#define MMA_BF16(d, a, b)                                                     \
    asm volatile("mma.sync.aligned.m16n8k16.row.col.f32.bf16.bf16.f32 "       \
                 "{%0,%1,%2,%3},{%4,%5,%6,%7},{%8,%9},{%0,%1,%2,%3};\n"       \
                 : "+f"(d[0]), "+f"(d[1]), "+f"(d[2]), "+f"(d[3])             \
                 : "r"(a[0]), "r"(a[1]), "r"(a[2]), "r"(a[3]),                \
                   "r"(b[0]), "r"(b[1]))

// ---------------- LayerNorm: one block (256 thr) per row; emits bf16 ----------------
__global__ __launch_bounds__(256) void ln_kernel(const float* __restrict__ x,
                                                 const float* __restrict__ gamma,
                                                 const float* __restrict__ beta) {
    int row = blockIdx.x;
    int tid = threadIdx.x;
    const float4* xr = (const float4*)(x + (size_t)row * Hh);
    float4 v = xr[tid];

    __shared__ float red[8];
    float s = v.x + v.y + v.z + v.w;
    #pragma unroll
    for (int o = 16; o; o >>= 1) s += __shfl_xor_sync(0xffffffffu, s, o);
    if ((tid & 31) == 0) red[tid >> 5] = s;
    __syncthreads();
    if (tid < 8) {
        float t = red[tid];
        #pragma unroll
        for (int o = 4; o; o >>= 1) t += __shfl_xor_sync(0xffu, t, o);
        if (tid == 0) red[0] = t;
    }
    __syncthreads();
    float mu = red[0] * (1.0f / Hh);
    __syncthreads();
    float dx = v.x - mu, dy = v.y - mu, dz = v.z - mu, dw = v.w - mu;
    float ss = dx*dx + dy*dy + dz*dz + dw*dw;
    #pragma unroll
    for (int o = 16; o; o >>= 1) ss += __shfl_xor_sync(0xffffffffu, ss, o);
    if ((tid & 31) == 0) red[tid >> 5] = ss;
    __syncthreads();
    if (tid < 8) {
        float t = red[tid];
        #pragma unroll
        for (int o = 4; o; o >>= 1) t += __shfl_xor_sync(0xffu, t, o);
        if (tid == 0) red[0] = t;
    }
    __syncthreads();
    float var = red[0] * (1.0f / Hh);
    float rstd = rsqrtf(var + 1e-5f);

    float4 gm = ((const float4*)gamma)[tid];
    float4 bt = ((const float4*)beta)[tid];
    float ox = dx * rstd * gm.x + bt.x;
    float oy = dy * rstd * gm.y + bt.y;
    float oz = dz * rstd * gm.z + bt.z;
    float ow = dw * rstd * gm.w + bt.w;

    __nv_bfloat162* ch = (__nv_bfloat162*)(g_cnh + (size_t)row * Hh);
    ch[2 * tid]     = __floats2bfloat162_rn(ox, oy);
    ch[2 * tid + 1] = __floats2bfloat162_rn(oz, ow);
}

// ---------------- fused weight convert + bias dots ----------------
__global__ __launch_bounds__(256) void convbias_kernel(const float* __restrict__ Wq,
                                                       const float* __restrict__ bk,
                                                       const float* __restrict__ Wk,
                                                       const float* __restrict__ bq) {
    int gw = (blockIdx.x * blockDim.x + threadIdx.x) >> 5;
    int lane = threadIdx.x & 31;
    if (gw > 2048) return;

    if (gw == 2048) {
        float acc = 0.f;
        #pragma unroll
        for (int it = 0; it < 8; it++) {
            int c = it * 128 + lane * 4;
            float4 a = *(const float4*)(bq + c);
            float4 v = *(const float4*)(bk + c);
            acc += a.x * v.x + a.y * v.y + a.z * v.z + a.w * v.w;
        }
        #pragma unroll
        for (int o = 16; o; o >>= 1) acc += __shfl_xor_sync(0xffffffffu, acc, o);
        if (lane == 0) g_bqbk = acc;
        return;
    }

    const float* row; const float* vec; __nv_bfloat16* dsth;
    int r;
    if (gw < 1024) { r = gw;        row = Wq + (size_t)r * Hh; vec = bk; dsth = g_wqh + (size_t)r * Hh; }
    else           { r = gw - 1024; row = Wk + (size_t)r * Hh; vec = bq; dsth = g_wkh + (size_t)r * Hh; }

    float acc = 0.f;
    #pragma unroll
    for (int it = 0; it < 8; it++) {
        int c = it * 128 + lane * 4;
        float4 a = *(const float4*)(row + c);
        float4 v = *(const float4*)(vec + c);
        acc += a.x * v.x + a.y * v.y + a.z * v.z + a.w * v.w;
        __nv_bfloat162* d2 = (__nv_bfloat162*)(dsth + c);
        d2[0] = __floats2bfloat162_rn(a.x, a.y);
        d2[1] = __floats2bfloat162_rn(a.z, a.w);
    }
    #pragma unroll
    for (int o = 16; o; o >>= 1) acc += __shfl_xor_sync(0xffffffffu, acc, o);
    if (lane == 0) {
        if (gw < 1024) g_wqb[r] = acc;
        else           g_wkb[r] = acc;
    }
}

// ---------------- bf16 NT GEMM, 128x128 tile, 8 warps, 4-stage pipeline ----------------
// wait_group 2 keeps 2 loads in flight past the wait; fragment regs double-buffered
// across the 4 k16 steps of each 64-K chunk.
__global__ __launch_bounds__(256) void gemm_bf16_nt(const __nv_bfloat16* __restrict__ Aop,
                                                    const __nv_bfloat16* __restrict__ Bop,
                                                    __nv_bfloat16* __restrict__ C,
                                                    int N, int K) {
    extern __shared__ uint32_t smemw[];
    const int STAGEW = 8192;                 // words per stage (A 4096 + B 4096)
    int tid = threadIdx.x;
    int lane = tid & 31, warp = tid >> 5;
    int wy = warp >> 2, wx = warp & 3;

    const __nv_bfloat16* Abase = Aop + (size_t)blockIdx.y * 128 * K;
    const __nv_bfloat16* Bbase = Bop + (size_t)blockIdx.x * 128 * K;

    uint32_t sbase = smem_u32(smemw);

    float acc[4][4][4];
    #pragma unroll
    for (int i = 0; i < 4; i++)
        #pragma unroll
        for (int j = 0; j < 4; j++)
            #pragma unroll
            for (int r = 0; r < 4; r++) acc[i][j][r] = 0.f;

    int mrow = tid >> 3;
    int c4   = tid & 7;
    int c4x  = c4 ^ (mrow & 7);
    const __nv_bfloat16* Asrc = Abase + (size_t)mrow * K + 8 * c4;
    const __nv_bfloat16* Bsrc = Bbase + (size_t)mrow * K + 8 * c4;
    uint32_t Adst = sbase + (uint32_t)(mrow * 32 + 4 * c4x) * 4u;
    uint32_t Bdst = Adst + 16384u;
    const uint32_t STAGEB = 32768u;

    int ntiles = K >> 6;                     // 16 chunks of K=64

    auto load_stage = [&](int slot, int k0) {
        uint32_t so = (uint32_t)slot * STAGEB;
        #pragma unroll
        for (int r = 0; r < 4; r++) {
            cp16(Adst + so + (uint32_t)r * 4096u, Asrc + (size_t)(32 * r) * K + k0);
            cp16(Bdst + so + (uint32_t)r * 4096u, Bsrc + (size_t)(32 * r) * K + k0);
        }
        asm volatile("cp.async.commit_group;\n");
    };

    load_stage(0, 0);
    load_stage(1, 64);
    load_stage(2, 128);

    int q = lane >> 2, rsel = lane & 3;
    int sw = 4 * q;

    // fragment double buffers
    uint32_t afr[2][4][4], bfr[2][4][2];

    auto load_frags = [&](const uint32_t* sA, const uint32_t* sB, int kkstep, int buf) {
        int col0 = (kkstep * 8 + rsel) ^ sw;
        int col1 = col0 ^ 4;
        #pragma unroll
        for (int mt = 0; mt < 4; mt++) {
            int m0 = wy * 64 + mt * 16 + q;
            afr[buf][mt][0] = sA[m0 * 32 + col0];
            afr[buf][mt][1] = sA[(m0 + 8) * 32 + col0];
            afr[buf][mt][2] = sA[m0 * 32 + col1];
            afr[buf][mt][3] = sA[(m0 + 8) * 32 + col1];
        }
        #pragma unroll
        for (int nt = 0; nt < 4; nt++) {
            int n0 = wx * 32 + nt * 8 + q;
            bfr[buf][nt][0] = sB[n0 * 32 + col0];
            bfr[buf][nt][1] = sB[n0 * 32 + col1];
        }
    };

    for (int t = 0; t < ntiles; t++) {
        asm volatile("cp.async.wait_group 2;\n" ::: "memory");
        __syncthreads();

        const uint32_t* sA = smemw + (t & 3) * STAGEW;
        const uint32_t* sB = sA + 4096;

        load_frags(sA, sB, 0, 0);
        #pragma unroll
        for (int kkstep = 0; kkstep < 4; kkstep++) {
            int cur = kkstep & 1;
            if (kkstep < 3) load_frags(sA, sB, kkstep + 1, cur ^ 1);
            #pragma unroll
            for (int mt = 0; mt < 4; mt++)
                #pragma unroll
                for (int nt = 0; nt < 4; nt++)
                    MMA_BF16(acc[mt][nt], afr[cur][mt], bfr[cur][nt]);
        }

        if (t + 3 < ntiles) load_stage((t + 3) & 3, (t + 3) * 64);
    }
    asm volatile("cp.async.wait_group 0;\n" ::: "memory");

    #pragma unroll
    for (int mt = 0; mt < 4; mt++) {
        int r0 = blockIdx.y * 128 + wy * 64 + mt * 16 + (lane >> 2);
        #pragma unroll
        for (int nt = 0; nt < 4; nt++) {
            int cc = blockIdx.x * 128 + wx * 32 + nt * 8 + 2 * (lane & 3);
            *(__nv_bfloat162*)(C + (size_t)r0 * N + cc) =
                __floats2bfloat162_rn(acc[mt][nt][0], acc[mt][nt][1]);
            *(__nv_bfloat162*)(C + (size_t)(r0 + 8) * N + cc) =
                __floats2bfloat162_rn(acc[mt][nt][2], acc[mt][nt][3]);
        }
    }
}

// ---------------- bf16 NT GEMM, 64x64 tile, 4 warps, 3-stage; bf16 out (small GEMM) ----------------
__global__ __launch_bounds__(128) void gemm_bf16_nt64(const __nv_bfloat16* __restrict__ Aop,
                                                      const __nv_bfloat16* __restrict__ Bop,
                                                      __nv_bfloat16* __restrict__ C,
                                                      int N, int K) {
    extern __shared__ uint32_t smemw[];
    const int STAGEW = 4096;
    int tid = threadIdx.x;
    int lane = tid & 31, warp = tid >> 5;
    int wy = warp >> 1, wx = warp & 1;

    const __nv_bfloat16* Abase = Aop + (size_t)blockIdx.y * 64 * K;
    const __nv_bfloat16* Bbase = Bop + (size_t)blockIdx.x * 64 * K;

    uint32_t sbase = smem_u32(smemw);

    float acc[2][4][4];
    #pragma unroll
    for (int i = 0; i < 2; i++)
        #pragma unroll
        for (int j = 0; j < 4; j++)
            #pragma unroll
            for (int r = 0; r < 4; r++) acc[i][j][r] = 0.f;

    int mrow = tid >> 3;
    int c4   = tid & 7;
    int c4x  = c4 ^ (mrow & 7);
    const __nv_bfloat16* Asrc = Abase + (size_t)mrow * K + 8 * c4;
    const __nv_bfloat16* Bsrc = Bbase + (size_t)mrow * K + 8 * c4;
    uint32_t Adst = sbase + (uint32_t)(mrow * 32 + 4 * c4x) * 4u;
    uint32_t Bdst = Adst + 8192u;
    const uint32_t STAGEB = 16384u;

    int ntiles = K >> 6;

    auto load_stage = [&](int slot, int k0) {
        uint32_t so = (uint32_t)slot * STAGEB;
        #pragma unroll
        for (int r = 0; r < 4; r++) {
            cp16(Adst + so + (uint32_t)r * 2048u, Asrc + (size_t)(16 * r) * K + k0);
            cp16(Bdst + so + (uint32_t)r * 2048u, Bsrc + (size_t)(16 * r) * K + k0);
        }
        asm volatile("cp.async.commit_group;\n");
    };

    load_stage(0, 0);
    load_stage(1, 64);

    int q = lane >> 2, rsel = lane & 3;
    int sw = 4 * q;

    for (int t = 0; t < ntiles; t++) {
        asm volatile("cp.async.wait_group 1;\n");
        __syncthreads();

        int cur = t % 3;
        const uint32_t* sA = smemw + cur * STAGEW;
        const uint32_t* sB = sA + 2048;

        #pragma unroll
        for (int kk = 0; kk < 32; kk += 8) {
            int col0 = (kk + rsel) ^ sw;
            int col1 = col0 ^ 4;
            uint32_t a[2][4], b[4][2];
            #pragma unroll
            for (int mt = 0; mt < 2; mt++) {
                int m0 = wy * 32 + mt * 16 + q;
                a[mt][0] = sA[m0 * 32 + col0];
                a[mt][1] = sA[(m0 + 8) * 32 + col0];
                a[mt][2] = sA[m0 * 32 + col1];
                a[mt][3] = sA[(m0 + 8) * 32 + col1];
            }
            #pragma unroll
            for (int nt = 0; nt < 4; nt++) {
                int n0 = wx * 32 + nt * 8 + q;
                b[nt][0] = sB[n0 * 32 + col0];
                b[nt][1] = sB[n0 * 32 + col1];
            }
            #pragma unroll
            for (int mt = 0; mt < 2; mt++)
                #pragma unroll
                for (int nt = 0; nt < 4; nt++)
                    MMA_BF16(acc[mt][nt], a[mt], b[nt]);
        }

        __syncthreads();
        if (t + 2 < ntiles) load_stage((t + 2) % 3, (t + 2) * 64);
    }

    #pragma unroll
    for (int mt = 0; mt < 2; mt++) {
        int r0 = blockIdx.y * 64 + wy * 32 + mt * 16 + (lane >> 2);
        #pragma unroll
        for (int nt = 0; nt < 4; nt++) {
            int cc = blockIdx.x * 64 + wx * 32 + nt * 8 + 2 * (lane & 3);
            *(__nv_bfloat162*)(C + (size_t)r0 * N + cc) =
                __floats2bfloat162_rn(acc[mt][nt][0], acc[mt][nt][1]);
            *(__nv_bfloat162*)(C + (size_t)(r0 + 8) * N + cc) =
                __floats2bfloat162_rn(acc[mt][nt][2], acc[mt][nt][3]);
        }
    }
}

// ---------------- bf16 dot helper: 1024 elems across a warp ----------------
__device__ __forceinline__ float warp_dot_bf16(const __nv_bfloat16* __restrict__ a,
                                               const __nv_bfloat16* __restrict__ b,
                                               int lane) {
    float acc = 0.f;
    #pragma unroll
    for (int it = 0; it < 4; it++) {
        int c = it * 256 + lane * 8;
        uint4 aw = *(const uint4*)(a + c);
        uint4 bw = *(const uint4*)(b + c);
        const __nv_bfloat162* a2 = (const __nv_bfloat162*)&aw;
        const __nv_bfloat162* b2 = (const __nv_bfloat162*)&bw;
        #pragma unroll
        for (int j = 0; j < 4; j++) {
            float2 fa = __bfloat1622float2(a2[j]);
            float2 fb = __bfloat1622float2(b2[j]);
            acc += fa.x * fb.x + fa.y * fb.y;
        }
    }
    #pragma unroll
    for (int o = 16; o; o >>= 1) acc += __shfl_xor_sync(0xffffffffu, acc, o);
    return acc;
}

// ---------------- vq_i = cn_i . wqb, vk_i = cn_i . wkb ----------------
__global__ __launch_bounds__(256) void vqvk_kernel() {
    int gw = (blockIdx.x * blockDim.x + threadIdx.x) >> 5;
    int lane = threadIdx.x & 31;
    if (gw >= BS) return;
    const __nv_bfloat16* cni = g_cnh + (size_t)gw * Hh;
    float aq = 0.f, ak = 0.f;
    #pragma unroll
    for (int it = 0; it < 4; it++) {
        int c = it * 256 + lane * 8;
        uint4 xw = *(const uint4*)(cni + c);
        const __nv_bfloat162* x2 = (const __nv_bfloat162*)&xw;
        #pragma unroll
        for (int j = 0; j < 4; j++) {
            float2 fx = __bfloat1622float2(x2[j]);
            int cc = c + 2 * j;
            aq += fx.x * g_wqb[cc] + fx.y * g_wqb[cc + 1];
            ak += fx.x * g_wkb[cc] + fx.y * g_wkb[cc + 1];
        }
    }
    #pragma unroll
    for (int o = 16; o; o >>= 1) {
        aq += __shfl_xor_sync(0xffffffffu, aq, o);
        ak += __shfl_xor_sync(0xffffffffu, ak, o);
    }
    if (lane == 0) { g_vq[gw] = aq; g_vk[gw] = ak; }
}

// ---------------- adjacent-pair scores via u and cn (bf16): one warp per (b,i) ----------------
__global__ __launch_bounds__(256) void band_dots_kernel(const int* __restrict__ mask) {
    int gw = (blockIdx.x * blockDim.x + threadIdx.x) >> 5;
    int lane = threadIdx.x & 31;
    if (gw >= BS) return;
    int b = gw >> 10;
    int i = gw & (Ss - 1);
    const __nv_bfloat16* ui = g_uh + (size_t)gw * Hh;
    int padi = mask[(b << 10) + i];
    float su = -1e9f, sd = -1e9f;
    float bb = g_bqbk;

    if (i < Ss - 1 && padi && mask[(b << 10) + i + 1]) {
        float acc = warp_dot_bf16(ui, g_cnh + (size_t)(gw + 1) * Hh, lane);
        su = (acc + g_vq[gw] + g_vk[gw + 1] + bb) * (1.0f / 32.0f);
    }
    if (i > 0 && padi && mask[(b << 10) + i - 1]) {
        float acc = warp_dot_bf16(ui, g_cnh + (size_t)(gw - 1) * Hh, lane);
        sd = (acc + g_vq[gw] + g_vk[gw - 1] + bb) * (1.0f / 32.0f);
    }
    if (lane == 0) { g_sup[gw] = su; g_sdn[gw] = sd; }
}

// ---------------- fused 2-entry softmax + symmetric band ----------------
__global__ void band_kernel() {
    int idx = blockIdx.x * blockDim.x + threadIdx.x;
    if (idx >= BS) return;
    int i = idx & (Ss - 1);
    if (i >= Ss - 1) return;
    float su = g_sup[idx], sd = g_sdn[idx];
    float m = fmaxf(su, sd);
    float eu = expf(su - m), ed = expf(sd - m);
    float pup = eu / (eu + ed);
    float su2 = g_sup[idx + 1], sd2 = g_sdn[idx + 1];
    float m2 = fmaxf(su2, sd2);
    float eu2 = expf(su2 - m2), ed2 = expf(sd2 - m2);
    float pdn = ed2 / (eu2 + ed2);
    g_band[idx] = sqrtf(pup * pdn + 1e-9f);
}

// ---------------- fused output: one block per (b,row) ----------------
__global__ __launch_bounds__(256) void out_kernel(const float* __restrict__ prior,
                                                  const int* __restrict__ mask,
                                                  float* __restrict__ out,
                                                  int Nout) {
    int row = blockIdx.x;
    int b = row >> 10;
    int r = row & (Ss - 1);
    int tid = threadIdx.x;
    const float c0 = sqrtf(1e-9f);

    float4 p4 = ((const float4*)(prior + (size_t)row * Ss))[tid];
    int4  m4 = ((const int4*)(mask + (b << 10)))[tid];
    int padr = mask[(b << 10) + r];

    float pv[4] = {p4.x, p4.y, p4.z, p4.w};
    int   mc[4] = {m4.x, m4.y, m4.z, m4.w};
    int c_base = tid * 4;

    float nbo[4], graw[4];
    #pragma unroll
    for (int j = 0; j < 4; j++) {
        int c = c_base + j;
        float nbs = c0;
        if (r > 0 && c == r - 1)       nbs = g_band[(b << 10) + r - 1];
        if (r < Ss - 1 && c == r + 1)  nbs = g_band[(b << 10) + r];
        nbo[j]  = pv[j] + (1.0f - pv[j]) * nbs;
        graw[j] = (c == r) ? (2.0f + 1e-9f) : (1.0f + nbo[j]);
    }

    __shared__ float red[8];
    float s = graw[0] + graw[1] + graw[2] + graw[3];
    #pragma unroll
    for (int o = 16; o; o >>= 1) s += __shfl_xor_sync(0xffffffffu, s, o);
    if ((tid & 31) == 0) red[tid >> 5] = s;
    __syncthreads();
    if (tid < 8) {
        float t = red[tid];
        #pragma unroll
        for (int o = 4; o; o >>= 1) t += __shfl_xor_sync(0xffu, t, o);
        if (tid == 0) red[0] = t;
    }
    __syncthreads();
    float invD = 1.0f / (red[0] + 1e-9f);

    float4 go, no;
    float f0 = (padr && mc[0]) ? 1.0f : 0.0f;
    float f1 = (padr && mc[1]) ? 1.0f : 0.0f;
    float f2 = (padr && mc[2]) ? 1.0f : 0.0f;
    float f3 = (padr && mc[3]) ? 1.0f : 0.0f;
    go.x = graw[0] * invD * f0; no.x = nbo[0] * f0;
    go.y = graw[1] * invD * f1; no.y = nbo[1] * f1;
    go.z = graw[2] * invD * f2; no.z = nbo[2] * f2;
    go.w = graw[3] * invD * f3; no.w = nbo[3] * f3;

    size_t base = (size_t)row * Ss + c_base;
    *(float4*)(out + base)                = go;
    *(float4*)(out + (size_t)Nout + base) = no;
}

// ---------------- launch ----------------
extern "C" void kernel_launch(void* const* d_in, const int* in_sizes, int n_in,
                              void* d_out, int out_size) {
    const float* context = (const float*)d_in[0];
    const int*   mask    = (const int*)  d_in[1];
    const float* prior   = (const float*)d_in[2];
    const float* gamma   = (const float*)d_in[3];
    const float* beta    = (const float*)d_in[4];
    const float* Wk      = (const float*)d_in[5];
    const float* bk      = (const float*)d_in[6];
    const float* Wq      = (const float*)d_in[7];
    const float* bq      = (const float*)d_in[8];
    float* out = (float*)d_out;
    int Nout = out_size / 2;

    __nv_bfloat16 *cnh, *wkh, *wqh, *Ath, *uh;
    cudaGetSymbolAddress((void**)&cnh, g_cnh);
    cudaGetSymbolAddress((void**)&wkh, g_wkh);
    cudaGetSymbolAddress((void**)&wqh, g_wqh);
    cudaGetSymbolAddress((void**)&Ath, g_Ath);
    cudaGetSymbolAddress((void**)&uh,  g_uh);

    static int smem_set = 0;
    if (!smem_set) {
        cudaFuncSetAttribute(gemm_bf16_nt,   cudaFuncAttributeMaxDynamicSharedMemorySize, 131072);
        cudaFuncSetAttribute(gemm_bf16_nt64, cudaFuncAttributeMaxDynamicSharedMemorySize, 49152);
        smem_set = 1;
    }

    ln_kernel<<<BS, 256>>>(context, gamma, beta);
    convbias_kernel<<<257, 256>>>(Wq, bk, Wk, bq);

    // At[e,d] = sum_h Wk[e,h] * Wq[d,h]   (bf16 out, 64x64 tiles -> 256 CTAs)
    dim3 gsmall(Hh / 64, Hh / 64);
    gemm_bf16_nt64<<<gsmall, 128, 49152>>>(wkh, wqh, Ath, Hh, Hh);

    // u[i,e] = sum_d cn[i,d] * At[e,d]    (bf16 out, 4-stage pipeline)
    dim3 gbig(Hh / 128, BS / 128);
    gemm_bf16_nt<<<gbig, 256, 131072>>>(cnh, Ath, uh, Hh, Hh);

    vqvk_kernel<<<(BS * 32) / 256, 256>>>();
    band_dots_kernel<<<(BS * 32) / 256, 256>>>(mask);
    band_kernel<<<(BS + 255) / 256, 256>>>();

    out_kernel<<<BS, 256>>>(prior, mask, out, Nout);
}

// round 14
// speedup vs baseline: 6.7682x; 1.0484x over previous
#include <cuda_runtime.h>
#include <cuda_bf16.h>
#include <math.h>
#include <stdint.h>

#define Bb 8
#define Ss 1024
#define Hh 1024
#define BS (Bb*Ss)   // 8192

// ---------------- scratch (device globals; no allocation allowed) ----------------
__device__ __nv_bfloat16  g_cnh[(size_t)BS*Hh];   // layernorm output (bf16)
__device__ __nv_bfloat16  g_uh [(size_t)BS*Hh];   // u = cn @ (Wq Wk^T)  (bf16)
__device__ __nv_bfloat16  g_wkh[(size_t)Hh*Hh];
__device__ __nv_bfloat16  g_wqh[(size_t)Hh*Hh];
__device__ __nv_bfloat16  g_Ath[(size_t)Hh*Hh];   // At = Wk @ Wq^T (bf16)
__device__ float g_wqb[Hh];              // Wq @ bk
__device__ float g_wkb[Hh];              // Wk @ bq
__device__ float g_bqbk;
__device__ float g_vq[BS];
__device__ float g_vk[BS];
__device__ float g_sup[BS];
__device__ float g_sdn[BS];
__device__ float g_band[BS];

// ================= helpers =================
__device__ __forceinline__ uint32_t smem_u32(const void* p) {
    uint32_t a;
    asm("{ .reg .u64 t; cvta.to.shared.u64 t, %1; cvt.u32.u64 %0, t; }" : "=r"(a) : "l"(p));
    return a;
}
__device__ __forceinline__ void cp16(uint32_t dst, const void* src) {
    asm volatile("cp.async.cg.shared.global [%0], [%1], 16;\n" :: "r"(dst), "l"(src));
}
#define MMA_BF16(d, a, b)                                                     \
    asm volatile("mma.sync.aligned.m16n8k16.row.col.f32.bf16.bf16.f32 "       \
                 "{%0,%1,%2,%3},{%4,%5,%6,%7},{%8,%9},{%0,%1,%2,%3};\n"       \
                 : "+f"(d[0]), "+f"(d[1]), "+f"(d[2]), "+f"(d[3])             \
                 : "r"(a[0]), "r"(a[1]), "r"(a[2]), "r"(a[3]),                \
                   "r"(b[0]), "r"(b[1]))
#define LDSM_X4(r0, r1, r2, r3, addr)                                         \
    asm volatile("ldmatrix.sync.aligned.m8n8.x4.shared.b16 {%0,%1,%2,%3}, [%4];" \
                 : "=r"(r0), "=r"(r1), "=r"(r2), "=r"(r3) : "r"(addr))

// ---------------- LayerNorm: one block (256 thr) per row; emits bf16 ----------------
__global__ __launch_bounds__(256) void ln_kernel(const float* __restrict__ x,
                                                 const float* __restrict__ gamma,
                                                 const float* __restrict__ beta) {
    int row = blockIdx.x;
    int tid = threadIdx.x;
    const float4* xr = (const float4*)(x + (size_t)row * Hh);
    float4 v = xr[tid];

    __shared__ float red[8];
    float s = v.x + v.y + v.z + v.w;
    #pragma unroll
    for (int o = 16; o; o >>= 1) s += __shfl_xor_sync(0xffffffffu, s, o);
    if ((tid & 31) == 0) red[tid >> 5] = s;
    __syncthreads();
    if (tid < 8) {
        float t = red[tid];
        #pragma unroll
        for (int o = 4; o; o >>= 1) t += __shfl_xor_sync(0xffu, t, o);
        if (tid == 0) red[0] = t;
    }
    __syncthreads();
    float mu = red[0] * (1.0f / Hh);
    __syncthreads();
    float dx = v.x - mu, dy = v.y - mu, dz = v.z - mu, dw = v.w - mu;
    float ss = dx*dx + dy*dy + dz*dz + dw*dw;
    #pragma unroll
    for (int o = 16; o; o >>= 1) ss += __shfl_xor_sync(0xffffffffu, ss, o);
    if ((tid & 31) == 0) red[tid >> 5] = ss;
    __syncthreads();
    if (tid < 8) {
        float t = red[tid];
        #pragma unroll
        for (int o = 4; o; o >>= 1) t += __shfl_xor_sync(0xffu, t, o);
        if (tid == 0) red[0] = t;
    }
    __syncthreads();
    float var = red[0] * (1.0f / Hh);
    float rstd = rsqrtf(var + 1e-5f);

    float4 gm = ((const float4*)gamma)[tid];
    float4 bt = ((const float4*)beta)[tid];
    float ox = dx * rstd * gm.x + bt.x;
    float oy = dy * rstd * gm.y + bt.y;
    float oz = dz * rstd * gm.z + bt.z;
    float ow = dw * rstd * gm.w + bt.w;

    __nv_bfloat162* ch = (__nv_bfloat162*)(g_cnh + (size_t)row * Hh);
    ch[2 * tid]     = __floats2bfloat162_rn(ox, oy);
    ch[2 * tid + 1] = __floats2bfloat162_rn(oz, ow);
}

// ---------------- fused weight convert + bias dots ----------------
__global__ __launch_bounds__(256) void convbias_kernel(const float* __restrict__ Wq,
                                                       const float* __restrict__ bk,
                                                       const float* __restrict__ Wk,
                                                       const float* __restrict__ bq) {
    int gw = (blockIdx.x * blockDim.x + threadIdx.x) >> 5;
    int lane = threadIdx.x & 31;
    if (gw > 2048) return;

    if (gw == 2048) {
        float acc = 0.f;
        #pragma unroll
        for (int it = 0; it < 8; it++) {
            int c = it * 128 + lane * 4;
            float4 a = *(const float4*)(bq + c);
            float4 v = *(const float4*)(bk + c);
            acc += a.x * v.x + a.y * v.y + a.z * v.z + a.w * v.w;
        }
        #pragma unroll
        for (int o = 16; o; o >>= 1) acc += __shfl_xor_sync(0xffffffffu, acc, o);
        if (lane == 0) g_bqbk = acc;
        return;
    }

    const float* row; const float* vec; __nv_bfloat16* dsth;
    int r;
    if (gw < 1024) { r = gw;        row = Wq + (size_t)r * Hh; vec = bk; dsth = g_wqh + (size_t)r * Hh; }
    else           { r = gw - 1024; row = Wk + (size_t)r * Hh; vec = bq; dsth = g_wkh + (size_t)r * Hh; }

    float acc = 0.f;
    #pragma unroll
    for (int it = 0; it < 8; it++) {
        int c = it * 128 + lane * 4;
        float4 a = *(const float4*)(row + c);
        float4 v = *(const float4*)(vec + c);
        acc += a.x * v.x + a.y * v.y + a.z * v.z + a.w * v.w;
        __nv_bfloat162* d2 = (__nv_bfloat162*)(dsth + c);
        d2[0] = __floats2bfloat162_rn(a.x, a.y);
        d2[1] = __floats2bfloat162_rn(a.z, a.w);
    }
    #pragma unroll
    for (int o = 16; o; o >>= 1) acc += __shfl_xor_sync(0xffffffffu, acc, o);
    if (lane == 0) {
        if (gw < 1024) g_wqb[r] = acc;
        else           g_wkb[r] = acc;
    }
}

// ---------------- bf16 NT GEMM, 128x128 tile, 8 warps, 3-stage, ldmatrix, 2 CTA/SM ----------------
__global__ void __launch_bounds__(256, 2) gemm_bf16_nt(const __nv_bfloat16* __restrict__ Aop,
                                                       const __nv_bfloat16* __restrict__ Bop,
                                                       __nv_bfloat16* __restrict__ C,
                                                       int N, int K) {
    extern __shared__ uint32_t smemw[];
    int tid = threadIdx.x;
    int lane = tid & 31, warp = tid >> 5;
    int wy = warp >> 2, wx = warp & 3;

    const __nv_bfloat16* Abase = Aop + (size_t)blockIdx.y * 128 * K;
    const __nv_bfloat16* Bbase = Bop + (size_t)blockIdx.x * 128 * K;

    uint32_t sbase = smem_u32(smemw);
    const uint32_t STAGEB = 32768u;          // A 16KB + B 16KB per stage

    float acc[4][4][4];
    #pragma unroll
    for (int i = 0; i < 4; i++)
        #pragma unroll
        for (int j = 0; j < 4; j++)
            #pragma unroll
            for (int r = 0; r < 4; r++) acc[i][j][r] = 0.f;

    // global->smem store mapping (16B granules, XOR swizzle)
    int mrow = tid >> 3;
    int c4   = tid & 7;
    int c4x  = c4 ^ (mrow & 7);
    const __nv_bfloat16* Asrc = Abase + (size_t)mrow * K + 8 * c4;
    const __nv_bfloat16* Bsrc = Bbase + (size_t)mrow * K + 8 * c4;
    uint32_t Adst = sbase + (uint32_t)(mrow * 128 + c4x * 16);
    uint32_t Bdst = Adst + 16384u;

    int ntiles = K >> 6;                     // 16 chunks of K=64

    auto load_stage = [&](int slot, int k0) {
        uint32_t so = (uint32_t)slot * STAGEB;
        #pragma unroll
        for (int r = 0; r < 4; r++) {
            cp16(Adst + so + (uint32_t)r * 4096u, Asrc + (size_t)(32 * r) * K + k0);
            cp16(Bdst + so + (uint32_t)r * 4096u, Bsrc + (size_t)(32 * r) * K + k0);
        }
        asm volatile("cp.async.commit_group;\n");
    };

    load_stage(0, 0);
    load_stage(1, 64);

    // ldmatrix per-lane address precompute
    int sel = lane >> 3, ri = lane & 7;      // tile select, row-in-tile
    int gselA = sel >> 1;                    // A: k-granule select
    int gselB = sel & 1;                     // B: k-granule select
    uint32_t rowA[4], rowB[2];
    #pragma unroll
    for (int mt = 0; mt < 4; mt++) {
        int rA = wy * 64 + mt * 16 + (sel & 1) * 8 + ri;
        rowA[mt] = (uint32_t)(rA * 128);
    }
    #pragma unroll
    for (int p = 0; p < 2; p++) {
        int rB = wx * 32 + p * 16 + (sel >> 1) * 8 + ri;
        rowB[p] = 16384u + (uint32_t)(rB * 128);
    }

    for (int t = 0; t < ntiles; t++) {
        if (t + 1 < ntiles) asm volatile("cp.async.wait_group 1;\n" ::: "memory");
        else                asm volatile("cp.async.wait_group 0;\n" ::: "memory");
        __syncthreads();

        if (t + 2 < ntiles) load_stage((t + 2) % 3, (t + 2) * 64);

        uint32_t sb = sbase + (uint32_t)(t % 3) * STAGEB;

        #pragma unroll
        for (int kkstep = 0; kkstep < 4; kkstep++) {
            int kk2 = kkstep * 2;
            uint32_t a[4][4], b[4][2];
            uint32_t offA = (uint32_t)(((kk2 + gselA) ^ ri) << 4);
            uint32_t offB = (uint32_t)(((kk2 + gselB) ^ ri) << 4);
            #pragma unroll
            for (int mt = 0; mt < 4; mt++)
                LDSM_X4(a[mt][0], a[mt][1], a[mt][2], a[mt][3], sb + rowA[mt] + offA);
            #pragma unroll
            for (int p = 0; p < 2; p++)
                LDSM_X4(b[2*p][0], b[2*p][1], b[2*p+1][0], b[2*p+1][1], sb + rowB[p] + offB);
            #pragma unroll
            for (int mt = 0; mt < 4; mt++)
                #pragma unroll
                for (int nt = 0; nt < 4; nt++)
                    MMA_BF16(acc[mt][nt], a[mt], b[nt]);
        }
    }

    #pragma unroll
    for (int mt = 0; mt < 4; mt++) {
        int r0 = blockIdx.y * 128 + wy * 64 + mt * 16 + (lane >> 2);
        #pragma unroll
        for (int nt = 0; nt < 4; nt++) {
            int cc = blockIdx.x * 128 + wx * 32 + nt * 8 + 2 * (lane & 3);
            *(__nv_bfloat162*)(C + (size_t)r0 * N + cc) =
                __floats2bfloat162_rn(acc[mt][nt][0], acc[mt][nt][1]);
            *(__nv_bfloat162*)(C + (size_t)(r0 + 8) * N + cc) =
                __floats2bfloat162_rn(acc[mt][nt][2], acc[mt][nt][3]);
        }
    }
}

// ---------------- bf16 NT GEMM, 64x64 tile, 4 warps, 3-stage; bf16 out (small GEMM) ----------------
__global__ __launch_bounds__(128) void gemm_bf16_nt64(const __nv_bfloat16* __restrict__ Aop,
                                                      const __nv_bfloat16* __restrict__ Bop,
                                                      __nv_bfloat16* __restrict__ C,
                                                      int N, int K) {
    extern __shared__ uint32_t smemw[];
    const int STAGEW = 4096;
    int tid = threadIdx.x;
    int lane = tid & 31, warp = tid >> 5;
    int wy = warp >> 1, wx = warp & 1;

    const __nv_bfloat16* Abase = Aop + (size_t)blockIdx.y * 64 * K;
    const __nv_bfloat16* Bbase = Bop + (size_t)blockIdx.x * 64 * K;

    uint32_t sbase = smem_u32(smemw);

    float acc[2][4][4];
    #pragma unroll
    for (int i = 0; i < 2; i++)
        #pragma unroll
        for (int j = 0; j < 4; j++)
            #pragma unroll
            for (int r = 0; r < 4; r++) acc[i][j][r] = 0.f;

    int mrow = tid >> 3;
    int c4   = tid & 7;
    int c4x  = c4 ^ (mrow & 7);
    const __nv_bfloat16* Asrc = Abase + (size_t)mrow * K + 8 * c4;
    const __nv_bfloat16* Bsrc = Bbase + (size_t)mrow * K + 8 * c4;
    uint32_t Adst = sbase + (uint32_t)(mrow * 32 + 4 * c4x) * 4u;
    uint32_t Bdst = Adst + 8192u;
    const uint32_t STAGEB = 16384u;

    int ntiles = K >> 6;

    auto load_stage = [&](int slot, int k0) {
        uint32_t so = (uint32_t)slot * STAGEB;
        #pragma unroll
        for (int r = 0; r < 4; r++) {
            cp16(Adst + so + (uint32_t)r * 2048u, Asrc + (size_t)(16 * r) * K + k0);
            cp16(Bdst + so + (uint32_t)r * 2048u, Bsrc + (size_t)(16 * r) * K + k0);
        }
        asm volatile("cp.async.commit_group;\n");
    };

    load_stage(0, 0);
    load_stage(1, 64);

    int q = lane >> 2, rsel = lane & 3;
    int sw = 4 * q;

    for (int t = 0; t < ntiles; t++) {
        if (t + 1 < ntiles) asm volatile("cp.async.wait_group 1;\n" ::: "memory");
        else                asm volatile("cp.async.wait_group 0;\n" ::: "memory");
        __syncthreads();

        if (t + 2 < ntiles) load_stage((t + 2) % 3, (t + 2) * 64);

        int cur = t % 3;
        const uint32_t* sA = smemw + cur * STAGEW;
        const uint32_t* sB = sA + 2048;

        #pragma unroll
        for (int kk = 0; kk < 32; kk += 8) {
            int col0 = (kk + rsel) ^ sw;
            int col1 = col0 ^ 4;
            uint32_t a[2][4], b[4][2];
            #pragma unroll
            for (int mt = 0; mt < 2; mt++) {
                int m0 = wy * 32 + mt * 16 + q;
                a[mt][0] = sA[m0 * 32 + col0];
                a[mt][1] = sA[(m0 + 8) * 32 + col0];
                a[mt][2] = sA[m0 * 32 + col1];
                a[mt][3] = sA[(m0 + 8) * 32 + col1];
            }
            #pragma unroll
            for (int nt = 0; nt < 4; nt++) {
                int n0 = wx * 32 + nt * 8 + q;
                b[nt][0] = sB[n0 * 32 + col0];
                b[nt][1] = sB[n0 * 32 + col1];
            }
            #pragma unroll
            for (int mt = 0; mt < 2; mt++)
                #pragma unroll
                for (int nt = 0; nt < 4; nt++)
                    MMA_BF16(acc[mt][nt], a[mt], b[nt]);
        }
    }

    #pragma unroll
    for (int mt = 0; mt < 2; mt++) {
        int r0 = blockIdx.y * 64 + wy * 32 + mt * 16 + (lane >> 2);
        #pragma unroll
        for (int nt = 0; nt < 4; nt++) {
            int cc = blockIdx.x * 64 + wx * 32 + nt * 8 + 2 * (lane & 3);
            *(__nv_bfloat162*)(C + (size_t)r0 * N + cc) =
                __floats2bfloat162_rn(acc[mt][nt][0], acc[mt][nt][1]);
            *(__nv_bfloat162*)(C + (size_t)(r0 + 8) * N + cc) =
                __floats2bfloat162_rn(acc[mt][nt][2], acc[mt][nt][3]);
        }
    }
}

// ---------------- bf16 dot helper: 1024 elems across a warp ----------------
__device__ __forceinline__ float warp_dot_bf16(const __nv_bfloat16* __restrict__ a,
                                               const __nv_bfloat16* __restrict__ b,
                                               int lane) {
    float acc = 0.f;
    #pragma unroll
    for (int it = 0; it < 4; it++) {
        int c = it * 256 + lane * 8;
        uint4 aw = *(const uint4*)(a + c);
        uint4 bw = *(const uint4*)(b + c);
        const __nv_bfloat162* a2 = (const __nv_bfloat162*)&aw;
        const __nv_bfloat162* b2 = (const __nv_bfloat162*)&bw;
        #pragma unroll
        for (int j = 0; j < 4; j++) {
            float2 fa = __bfloat1622float2(a2[j]);
            float2 fb = __bfloat1622float2(b2[j]);
            acc += fa.x * fb.x + fa.y * fb.y;
        }
    }
    #pragma unroll
    for (int o = 16; o; o >>= 1) acc += __shfl_xor_sync(0xffffffffu, acc, o);
    return acc;
}

// ---------------- vq_i = cn_i . wqb, vk_i = cn_i . wkb ----------------
__global__ __launch_bounds__(256) void vqvk_kernel() {
    int gw = (blockIdx.x * blockDim.x + threadIdx.x) >> 5;
    int lane = threadIdx.x & 31;
    if (gw >= BS) return;
    const __nv_bfloat16* cni = g_cnh + (size_t)gw * Hh;
    float aq = 0.f, ak = 0.f;
    #pragma unroll
    for (int it = 0; it < 4; it++) {
        int c = it * 256 + lane * 8;
        uint4 xw = *(const uint4*)(cni + c);
        const __nv_bfloat162* x2 = (const __nv_bfloat162*)&xw;
        #pragma unroll
        for (int j = 0; j < 4; j++) {
            float2 fx = __bfloat1622float2(x2[j]);
            int cc = c + 2 * j;
            aq += fx.x * g_wqb[cc] + fx.y * g_wqb[cc + 1];
            ak += fx.x * g_wkb[cc] + fx.y * g_wkb[cc + 1];
        }
    }
    #pragma unroll
    for (int o = 16; o; o >>= 1) {
        aq += __shfl_xor_sync(0xffffffffu, aq, o);
        ak += __shfl_xor_sync(0xffffffffu, ak, o);
    }
    if (lane == 0) { g_vq[gw] = aq; g_vk[gw] = ak; }
}

// ---------------- adjacent-pair scores via u and cn (bf16): one warp per (b,i) ----------------
__global__ __launch_bounds__(256) void band_dots_kernel(const int* __restrict__ mask) {
    int gw = (blockIdx.x * blockDim.x + threadIdx.x) >> 5;
    int lane = threadIdx.x & 31;
    if (gw >= BS) return;
    int b = gw >> 10;
    int i = gw & (Ss - 1);
    const __nv_bfloat16* ui = g_uh + (size_t)gw * Hh;
    int padi = mask[(b << 10) + i];
    float su = -1e9f, sd = -1e9f;
    float bb = g_bqbk;

    if (i < Ss - 1 && padi && mask[(b << 10) + i + 1]) {
        float acc = warp_dot_bf16(ui, g_cnh + (size_t)(gw + 1) * Hh, lane);
        su = (acc + g_vq[gw] + g_vk[gw + 1] + bb) * (1.0f / 32.0f);
    }
    if (i > 0 && padi && mask[(b << 10) + i - 1]) {
        float acc = warp_dot_bf16(ui, g_cnh + (size_t)(gw - 1) * Hh, lane);
        sd = (acc + g_vq[gw] + g_vk[gw - 1] + bb) * (1.0f / 32.0f);
    }
    if (lane == 0) { g_sup[gw] = su; g_sdn[gw] = sd; }
}

// ---------------- fused 2-entry softmax + symmetric band ----------------
__global__ void band_kernel() {
    int idx = blockIdx.x * blockDim.x + threadIdx.x;
    if (idx >= BS) return;
    int i = idx & (Ss - 1);
    if (i >= Ss - 1) return;
    float su = g_sup[idx], sd = g_sdn[idx];
    float m = fmaxf(su, sd);
    float eu = expf(su - m), ed = expf(sd - m);
    float pup = eu / (eu + ed);
    float su2 = g_sup[idx + 1], sd2 = g_sdn[idx + 1];
    float m2 = fmaxf(su2, sd2);
    float eu2 = expf(su2 - m2), ed2 = expf(sd2 - m2);
    float pdn = ed2 / (eu2 + ed2);
    g_band[idx] = sqrtf(pup * pdn + 1e-9f);
}

// ---------------- fused output: one block per (b,row) ----------------
__global__ __launch_bounds__(256) void out_kernel(const float* __restrict__ prior,
                                                  const int* __restrict__ mask,
                                                  float* __restrict__ out,
                                                  int Nout) {
    int row = blockIdx.x;
    int b = row >> 10;
    int r = row & (Ss - 1);
    int tid = threadIdx.x;
    const float c0 = sqrtf(1e-9f);

    float4 p4 = ((const float4*)(prior + (size_t)row * Ss))[tid];
    int4  m4 = ((const int4*)(mask + (b << 10)))[tid];
    int padr = mask[(b << 10) + r];

    float pv[4] = {p4.x, p4.y, p4.z, p4.w};
    int   mc[4] = {m4.x, m4.y, m4.z, m4.w};
    int c_base = tid * 4;

    float nbo[4], graw[4];
    #pragma unroll
    for (int j = 0; j < 4; j++) {
        int c = c_base + j;
        float nbs = c0;
        if (r > 0 && c == r - 1)       nbs = g_band[(b << 10) + r - 1];
        if (r < Ss - 1 && c == r + 1)  nbs = g_band[(b << 10) + r];
        nbo[j]  = pv[j] + (1.0f - pv[j]) * nbs;
        graw[j] = (c == r) ? (2.0f + 1e-9f) : (1.0f + nbo[j]);
    }

    __shared__ float red[8];
    float s = graw[0] + graw[1] + graw[2] + graw[3];
    #pragma unroll
    for (int o = 16; o; o >>= 1) s += __shfl_xor_sync(0xffffffffu, s, o);
    if ((tid & 31) == 0) red[tid >> 5] = s;
    __syncthreads();
    if (tid < 8) {
        float t = red[tid];
        #pragma unroll
        for (int o = 4; o; o >>= 1) t += __shfl_xor_sync(0xffu, t, o);
        if (tid == 0) red[0] = t;
    }
    __syncthreads();
    float invD = 1.0f / (red[0] + 1e-9f);

    float4 go, no;
    float f0 = (padr && mc[0]) ? 1.0f : 0.0f;
    float f1 = (padr && mc[1]) ? 1.0f : 0.0f;
    float f2 = (padr && mc[2]) ? 1.0f : 0.0f;
    float f3 = (padr && mc[3]) ? 1.0f : 0.0f;
    go.x = graw[0] * invD * f0; no.x = nbo[0] * f0;
    go.y = graw[1] * invD * f1; no.y = nbo[1] * f1;
    go.z = graw[2] * invD * f2; no.z = nbo[2] * f2;
    go.w = graw[3] * invD * f3; no.w = nbo[3] * f3;

    size_t base = (size_t)row * Ss + c_base;
    *(float4*)(out + base)                = go;
    *(float4*)(out + (size_t)Nout + base) = no;
}

// ---------------- launch ----------------
extern "C" void kernel_launch(void* const* d_in, const int* in_sizes, int n_in,
                              void* d_out, int out_size) {
    const float* context = (const float*)d_in[0];
    const int*   mask    = (const int*)  d_in[1];
    const float* prior   = (const float*)d_in[2];
    const float* gamma   = (const float*)d_in[3];
    const float* beta    = (const float*)d_in[4];
    const float* Wk      = (const float*)d_in[5];
    const float* bk      = (const float*)d_in[6];
    const float* Wq      = (const float*)d_in[7];
    const float* bq      = (const float*)d_in[8];
    float* out = (float*)d_out;
    int Nout = out_size / 2;

    __nv_bfloat16 *cnh, *wkh, *wqh, *Ath, *uh;
    cudaGetSymbolAddress((void**)&cnh, g_cnh);
    cudaGetSymbolAddress((void**)&wkh, g_wkh);
    cudaGetSymbolAddress((void**)&wqh, g_wqh);
    cudaGetSymbolAddress((void**)&Ath, g_Ath);
    cudaGetSymbolAddress((void**)&uh,  g_uh);

    static int smem_set = 0;
    if (!smem_set) {
        cudaFuncSetAttribute(gemm_bf16_nt,   cudaFuncAttributeMaxDynamicSharedMemorySize, 98304);
        cudaFuncSetAttribute(gemm_bf16_nt64, cudaFuncAttributeMaxDynamicSharedMemorySize, 49152);
        smem_set = 1;
    }

    ln_kernel<<<BS, 256>>>(context, gamma, beta);
    convbias_kernel<<<257, 256>>>(Wq, bk, Wk, bq);

    // At[e,d] = sum_h Wk[e,h] * Wq[d,h]   (bf16 out, 64x64 tiles -> 256 CTAs)
    dim3 gsmall(Hh / 64, Hh / 64);
    gemm_bf16_nt64<<<gsmall, 128, 49152>>>(wkh, wqh, Ath, Hh, Hh);

    // u[i,e] = sum_d cn[i,d] * At[e,d]    (bf16 out, ldmatrix + 3-stage, 2 CTA/SM)
    dim3 gbig(Hh / 128, BS / 128);
    gemm_bf16_nt<<<gbig, 256, 98304>>>(cnh, Ath, uh, Hh, Hh);

    vqvk_kernel<<<(BS * 32) / 256, 256>>>();
    band_dots_kernel<<<(BS * 32) / 256, 256>>>(mask);
    band_kernel<<<(BS + 255) / 256, 256>>>();

    out_kernel<<<BS, 256>>>(prior, mask, out, Nout);
}

// round 16
// speedup vs baseline: 6.9031x; 1.0199x over previous
#include <cuda_runtime.h>
#include <cuda_bf16.h>
#include <math.h>
#include <stdint.h>

#define Bb 8
#define Ss 1024
#define Hh 1024
#define BS (Bb*Ss)   // 8192

// ---------------- scratch (device globals; no allocation allowed) ----------------
__device__ __nv_bfloat16  g_cnh[(size_t)BS*Hh];   // layernorm output (bf16)
__device__ __nv_bfloat16  g_uh [(size_t)BS*Hh];   // u = cn @ (Wq Wk^T)  (bf16)
__device__ __nv_bfloat16  g_wkh[(size_t)Hh*Hh];
__device__ __nv_bfloat16  g_wqh[(size_t)Hh*Hh];
__device__ __nv_bfloat16  g_Ath[(size_t)Hh*Hh];   // At = Wk @ Wq^T (bf16)
__device__ float g_wqb[Hh];              // Wq @ bk
__device__ float g_wkb[Hh];              // Wk @ bq
__device__ float g_bqbk;
__device__ float g_sup[BS];
__device__ float g_sdn[BS];

// ================= helpers =================
__device__ __forceinline__ uint32_t smem_u32(const void* p) {
    uint32_t a;
    asm("{ .reg .u64 t; cvta.to.shared.u64 t, %1; cvt.u32.u64 %0, t; }" : "=r"(a) : "l"(p));
    return a;
}
__device__ __forceinline__ void cp16(uint32_t dst, const void* src) {
    asm volatile("cp.async.cg.shared.global [%0], [%1], 16;\n" :: "r"(dst), "l"(src));
}
#define MMA_BF16(d, a, b)                                                     \
    asm volatile("mma.sync.aligned.m16n8k16.row.col.f32.bf16.bf16.f32 "       \
                 "{%0,%1,%2,%3},{%4,%5,%6,%7},{%8,%9},{%0,%1,%2,%3};\n"       \
                 : "+f"(d[0]), "+f"(d[1]), "+f"(d[2]), "+f"(d[3])             \
                 : "r"(a[0]), "r"(a[1]), "r"(a[2]), "r"(a[3]),                \
                   "r"(b[0]), "r"(b[1]))
#define LDSM_X4(r0, r1, r2, r3, addr)                                         \
    asm volatile("ldmatrix.sync.aligned.m8n8.x4.shared.b16 {%0,%1,%2,%3}, [%4];" \
                 : "=r"(r0), "=r"(r1), "=r"(r2), "=r"(r3) : "r"(addr))

// ---------------- merged LayerNorm + weight-convert/bias kernel ----------------
// blocks [0, BS): LN row per block (256 thr).
// blocks [BS, BS+257): convbias, 8 warps/block over 2049 warp-slots.
__global__ __launch_bounds__(256) void ln_conv_kernel(const float* __restrict__ x,
                                                      const float* __restrict__ gamma,
                                                      const float* __restrict__ beta,
                                                      const float* __restrict__ Wq,
                                                      const float* __restrict__ bk,
                                                      const float* __restrict__ Wk,
                                                      const float* __restrict__ bq) {
    int tid = threadIdx.x;
    int lane = tid & 31;

    if (blockIdx.x < BS) {
        int row = blockIdx.x;
        const float4* xr = (const float4*)(x + (size_t)row * Hh);
        float4 v = xr[tid];

        __shared__ float red[8];
        float s = v.x + v.y + v.z + v.w;
        #pragma unroll
        for (int o = 16; o; o >>= 1) s += __shfl_xor_sync(0xffffffffu, s, o);
        if ((tid & 31) == 0) red[tid >> 5] = s;
        __syncthreads();
        if (tid < 8) {
            float t = red[tid];
            #pragma unroll
            for (int o = 4; o; o >>= 1) t += __shfl_xor_sync(0xffu, t, o);
            if (tid == 0) red[0] = t;
        }
        __syncthreads();
        float mu = red[0] * (1.0f / Hh);
        __syncthreads();
        float dx = v.x - mu, dy = v.y - mu, dz = v.z - mu, dw = v.w - mu;
        float ss = dx*dx + dy*dy + dz*dz + dw*dw;
        #pragma unroll
        for (int o = 16; o; o >>= 1) ss += __shfl_xor_sync(0xffffffffu, ss, o);
        if ((tid & 31) == 0) red[tid >> 5] = ss;
        __syncthreads();
        if (tid < 8) {
            float t = red[tid];
            #pragma unroll
            for (int o = 4; o; o >>= 1) t += __shfl_xor_sync(0xffu, t, o);
            if (tid == 0) red[0] = t;
        }
        __syncthreads();
        float var = red[0] * (1.0f / Hh);
        float rstd = rsqrtf(var + 1e-5f);

        float4 gm = ((const float4*)gamma)[tid];
        float4 bt = ((const float4*)beta)[tid];
        float ox = dx * rstd * gm.x + bt.x;
        float oy = dy * rstd * gm.y + bt.y;
        float oz = dz * rstd * gm.z + bt.z;
        float ow = dw * rstd * gm.w + bt.w;

        __nv_bfloat162* ch = (__nv_bfloat162*)(g_cnh + (size_t)row * Hh);
        ch[2 * tid]     = __floats2bfloat162_rn(ox, oy);
        ch[2 * tid + 1] = __floats2bfloat162_rn(oz, ow);
        return;
    }

    // convbias part
    int gw = (blockIdx.x - BS) * 8 + (tid >> 5);
    if (gw > 2048) return;

    if (gw == 2048) {
        float acc = 0.f;
        #pragma unroll
        for (int it = 0; it < 8; it++) {
            int c = it * 128 + lane * 4;
            float4 a = *(const float4*)(bq + c);
            float4 v = *(const float4*)(bk + c);
            acc += a.x * v.x + a.y * v.y + a.z * v.z + a.w * v.w;
        }
        #pragma unroll
        for (int o = 16; o; o >>= 1) acc += __shfl_xor_sync(0xffffffffu, acc, o);
        if (lane == 0) g_bqbk = acc;
        return;
    }

    const float* row; const float* vec; __nv_bfloat16* dsth;
    int r;
    if (gw < 1024) { r = gw;        row = Wq + (size_t)r * Hh; vec = bk; dsth = g_wqh + (size_t)r * Hh; }
    else           { r = gw - 1024; row = Wk + (size_t)r * Hh; vec = bq; dsth = g_wkh + (size_t)r * Hh; }

    float acc = 0.f;
    #pragma unroll
    for (int it = 0; it < 8; it++) {
        int c = it * 128 + lane * 4;
        float4 a = *(const float4*)(row + c);
        float4 v = *(const float4*)(vec + c);
        acc += a.x * v.x + a.y * v.y + a.z * v.z + a.w * v.w;
        __nv_bfloat162* d2 = (__nv_bfloat162*)(dsth + c);
        d2[0] = __floats2bfloat162_rn(a.x, a.y);
        d2[1] = __floats2bfloat162_rn(a.z, a.w);
    }
    #pragma unroll
    for (int o = 16; o; o >>= 1) acc += __shfl_xor_sync(0xffffffffu, acc, o);
    if (lane == 0) {
        if (gw < 1024) g_wqb[r] = acc;
        else           g_wkb[r] = acc;
    }
}

// ---------------- bf16 NT GEMM, 128x128 tile, 8 warps, 3-stage, ldmatrix, frag DB, 2 CTA/SM ----------------
__global__ void __launch_bounds__(256, 2) gemm_bf16_nt(const __nv_bfloat16* __restrict__ Aop,
                                                       const __nv_bfloat16* __restrict__ Bop,
                                                       __nv_bfloat16* __restrict__ C,
                                                       int N, int K) {
    extern __shared__ uint32_t smemw[];
    int tid = threadIdx.x;
    int lane = tid & 31, warp = tid >> 5;
    int wy = warp >> 2, wx = warp & 3;

    const __nv_bfloat16* Abase = Aop + (size_t)blockIdx.y * 128 * K;
    const __nv_bfloat16* Bbase = Bop + (size_t)blockIdx.x * 128 * K;

    uint32_t sbase = smem_u32(smemw);
    const uint32_t STAGEB = 32768u;

    float acc[4][4][4];
    #pragma unroll
    for (int i = 0; i < 4; i++)
        #pragma unroll
        for (int j = 0; j < 4; j++)
            #pragma unroll
            for (int r = 0; r < 4; r++) acc[i][j][r] = 0.f;

    int mrow = tid >> 3;
    int c4   = tid & 7;
    int c4x  = c4 ^ (mrow & 7);
    const __nv_bfloat16* Asrc = Abase + (size_t)mrow * K + 8 * c4;
    const __nv_bfloat16* Bsrc = Bbase + (size_t)mrow * K + 8 * c4;
    uint32_t Adst = sbase + (uint32_t)(mrow * 128 + c4x * 16);
    uint32_t Bdst = Adst + 16384u;

    int ntiles = K >> 6;

    auto load_stage = [&](int slot, int k0) {
        uint32_t so = (uint32_t)slot * STAGEB;
        #pragma unroll
        for (int r = 0; r < 4; r++) {
            cp16(Adst + so + (uint32_t)r * 4096u, Asrc + (size_t)(32 * r) * K + k0);
            cp16(Bdst + so + (uint32_t)r * 4096u, Bsrc + (size_t)(32 * r) * K + k0);
        }
        asm volatile("cp.async.commit_group;\n");
    };

    load_stage(0, 0);
    load_stage(1, 64);

    int sel = lane >> 3, ri = lane & 7;
    int gselA = sel >> 1;
    int gselB = sel & 1;
    uint32_t rowA[4], rowB[2];
    #pragma unroll
    for (int mt = 0; mt < 4; mt++) {
        int rA = wy * 64 + mt * 16 + (sel & 1) * 8 + ri;
        rowA[mt] = (uint32_t)(rA * 128);
    }
    #pragma unroll
    for (int p = 0; p < 2; p++) {
        int rB = wx * 32 + p * 16 + (sel >> 1) * 8 + ri;
        rowB[p] = 16384u + (uint32_t)(rB * 128);
    }

    uint32_t afr[2][4][4], bfr[2][4][2];

    for (int t = 0; t < ntiles; t++) {
        if (t + 1 < ntiles) asm volatile("cp.async.wait_group 1;\n" ::: "memory");
        else                asm volatile("cp.async.wait_group 0;\n" ::: "memory");
        __syncthreads();

        if (t + 2 < ntiles) load_stage((t + 2) % 3, (t + 2) * 64);

        uint32_t sb = sbase + (uint32_t)(t % 3) * STAGEB;

        auto ldfr = [&](int kkstep, int buf) {
            int kk2 = kkstep * 2;
            uint32_t offA = (uint32_t)(((kk2 + gselA) ^ ri) << 4);
            uint32_t offB = (uint32_t)(((kk2 + gselB) ^ ri) << 4);
            #pragma unroll
            for (int mt = 0; mt < 4; mt++)
                LDSM_X4(afr[buf][mt][0], afr[buf][mt][1], afr[buf][mt][2], afr[buf][mt][3],
                        sb + rowA[mt] + offA);
            #pragma unroll
            for (int p = 0; p < 2; p++)
                LDSM_X4(bfr[buf][2*p][0], bfr[buf][2*p][1], bfr[buf][2*p+1][0], bfr[buf][2*p+1][1],
                        sb + rowB[p] + offB);
        };

        ldfr(0, 0);
        #pragma unroll
        for (int kkstep = 0; kkstep < 4; kkstep++) {
            int cur = kkstep & 1;
            if (kkstep < 3) ldfr(kkstep + 1, cur ^ 1);
            #pragma unroll
            for (int mt = 0; mt < 4; mt++)
                #pragma unroll
                for (int nt = 0; nt < 4; nt++)
                    MMA_BF16(acc[mt][nt], afr[cur][mt], bfr[cur][nt]);
        }
    }

    #pragma unroll
    for (int mt = 0; mt < 4; mt++) {
        int r0 = blockIdx.y * 128 + wy * 64 + mt * 16 + (lane >> 2);
        #pragma unroll
        for (int nt = 0; nt < 4; nt++) {
            int cc = blockIdx.x * 128 + wx * 32 + nt * 8 + 2 * (lane & 3);
            *(__nv_bfloat162*)(C + (size_t)r0 * N + cc) =
                __floats2bfloat162_rn(acc[mt][nt][0], acc[mt][nt][1]);
            *(__nv_bfloat162*)(C + (size_t)(r0 + 8) * N + cc) =
                __floats2bfloat162_rn(acc[mt][nt][2], acc[mt][nt][3]);
        }
    }
}

// ---------------- bf16 NT GEMM, 64x64 tile, 4 warps, 3-stage; bf16 out (small GEMM) ----------------
__global__ __launch_bounds__(128) void gemm_bf16_nt64(const __nv_bfloat16* __restrict__ Aop,
                                                      const __nv_bfloat16* __restrict__ Bop,
                                                      __nv_bfloat16* __restrict__ C,
                                                      int N, int K) {
    extern __shared__ uint32_t smemw[];
    const int STAGEW = 4096;
    int tid = threadIdx.x;
    int lane = tid & 31, warp = tid >> 5;
    int wy = warp >> 1, wx = warp & 1;

    const __nv_bfloat16* Abase = Aop + (size_t)blockIdx.y * 64 * K;
    const __nv_bfloat16* Bbase = Bop + (size_t)blockIdx.x * 64 * K;

    uint32_t sbase = smem_u32(smemw);

    float acc[2][4][4];
    #pragma unroll
    for (int i = 0; i < 2; i++)
        #pragma unroll
        for (int j = 0; j < 4; j++)
            #pragma unroll
            for (int r = 0; r < 4; r++) acc[i][j][r] = 0.f;

    int mrow = tid >> 3;
    int c4   = tid & 7;
    int c4x  = c4 ^ (mrow & 7);
    const __nv_bfloat16* Asrc = Abase + (size_t)mrow * K + 8 * c4;
    const __nv_bfloat16* Bsrc = Bbase + (size_t)mrow * K + 8 * c4;
    uint32_t Adst = sbase + (uint32_t)(mrow * 32 + 4 * c4x) * 4u;
    uint32_t Bdst = Adst + 8192u;
    const uint32_t STAGEB = 16384u;

    int ntiles = K >> 6;

    auto load_stage = [&](int slot, int k0) {
        uint32_t so = (uint32_t)slot * STAGEB;
        #pragma unroll
        for (int r = 0; r < 4; r++) {
            cp16(Adst + so + (uint32_t)r * 2048u, Asrc + (size_t)(16 * r) * K + k0);
            cp16(Bdst + so + (uint32_t)r * 2048u, Bsrc + (size_t)(16 * r) * K + k0);
        }
        asm volatile("cp.async.commit_group;\n");
    };

    load_stage(0, 0);
    load_stage(1, 64);

    int q = lane >> 2, rsel = lane & 3;
    int sw = 4 * q;

    for (int t = 0; t < ntiles; t++) {
        if (t + 1 < ntiles) asm volatile("cp.async.wait_group 1;\n" ::: "memory");
        else                asm volatile("cp.async.wait_group 0;\n" ::: "memory");
        __syncthreads();

        if (t + 2 < ntiles) load_stage((t + 2) % 3, (t + 2) * 64);

        int cur = t % 3;
        const uint32_t* sA = smemw + cur * STAGEW;
        const uint32_t* sB = sA + 2048;

        #pragma unroll
        for (int kk = 0; kk < 32; kk += 8) {
            int col0 = (kk + rsel) ^ sw;
            int col1 = col0 ^ 4;
            uint32_t a[2][4], b[4][2];
            #pragma unroll
            for (int mt = 0; mt < 2; mt++) {
                int m0 = wy * 32 + mt * 16 + q;
                a[mt][0] = sA[m0 * 32 + col0];
                a[mt][1] = sA[(m0 + 8) * 32 + col0];
                a[mt][2] = sA[m0 * 32 + col1];
                a[mt][3] = sA[(m0 + 8) * 32 + col1];
            }
            #pragma unroll
            for (int nt = 0; nt < 4; nt++) {
                int n0 = wx * 32 + nt * 8 + q;
                b[nt][0] = sB[n0 * 32 + col0];
                b[nt][1] = sB[n0 * 32 + col1];
            }
            #pragma unroll
            for (int mt = 0; mt < 2; mt++)
                #pragma unroll
                for (int nt = 0; nt < 4; nt++)
                    MMA_BF16(acc[mt][nt], a[mt], b[nt]);
        }
    }

    #pragma unroll
    for (int mt = 0; mt < 2; mt++) {
        int r0 = blockIdx.y * 64 + wy * 32 + mt * 16 + (lane >> 2);
        #pragma unroll
        for (int nt = 0; nt < 4; nt++) {
            int cc = blockIdx.x * 64 + wx * 32 + nt * 8 + 2 * (lane & 3);
            *(__nv_bfloat162*)(C + (size_t)r0 * N + cc) =
                __floats2bfloat162_rn(acc[mt][nt][0], acc[mt][nt][1]);
            *(__nv_bfloat162*)(C + (size_t)(r0 + 8) * N + cc) =
                __floats2bfloat162_rn(acc[mt][nt][2], acc[mt][nt][3]);
        }
    }
}

// ---------------- fused dual dot: (u . cn) and (cn . wkb) in one pass ----------------
__device__ __forceinline__ void dot2_u_wkb(const __nv_bfloat16* __restrict__ u,
                                           const __nv_bfloat16* __restrict__ cn,
                                           int lane, float& d_ucn, float& d_cwkb) {
    float a1 = 0.f, a2 = 0.f;
    #pragma unroll
    for (int it = 0; it < 4; it++) {
        int c = it * 256 + lane * 8;
        uint4 uw = *(const uint4*)(u + c);
        uint4 cw = *(const uint4*)(cn + c);
        float4 w0 = *(const float4*)(g_wkb + c);
        float4 w1 = *(const float4*)(g_wkb + c + 4);
        const __nv_bfloat162* u2 = (const __nv_bfloat162*)&uw;
        const __nv_bfloat162* c2 = (const __nv_bfloat162*)&cw;
        float wk[8] = {w0.x, w0.y, w0.z, w0.w, w1.x, w1.y, w1.z, w1.w};
        #pragma unroll
        for (int j = 0; j < 4; j++) {
            float2 fu = __bfloat1622float2(u2[j]);
            float2 fc = __bfloat1622float2(c2[j]);
            a1 += fu.x * fc.x + fu.y * fc.y;
            a2 += fc.x * wk[2*j] + fc.y * wk[2*j + 1];
        }
    }
    #pragma unroll
    for (int o = 16; o; o >>= 1) {
        a1 += __shfl_xor_sync(0xffffffffu, a1, o);
        a2 += __shfl_xor_sync(0xffffffffu, a2, o);
    }
    d_ucn = a1; d_cwkb = a2;
}

__device__ __forceinline__ float dot_cn_wqb(const __nv_bfloat16* __restrict__ cn, int lane) {
    float acc = 0.f;
    #pragma unroll
    for (int it = 0; it < 4; it++) {
        int c = it * 256 + lane * 8;
        uint4 cw = *(const uint4*)(cn + c);
        float4 w0 = *(const float4*)(g_wqb + c);
        float4 w1 = *(const float4*)(g_wqb + c + 4);
        const __nv_bfloat162* c2 = (const __nv_bfloat162*)&cw;
        float wq[8] = {w0.x, w0.y, w0.z, w0.w, w1.x, w1.y, w1.z, w1.w};
        #pragma unroll
        for (int j = 0; j < 4; j++) {
            float2 fc = __bfloat1622float2(c2[j]);
            acc += fc.x * wq[2*j] + fc.y * wq[2*j + 1];
        }
    }
    #pragma unroll
    for (int o = 16; o; o >>= 1) acc += __shfl_xor_sync(0xffffffffu, acc, o);
    return acc;
}

// ---------------- adjacent-pair scores (vq/vk folded in): one warp per (b,i) ----------------
__global__ __launch_bounds__(256) void band_dots_kernel(const int* __restrict__ mask) {
    int gw = (blockIdx.x * blockDim.x + threadIdx.x) >> 5;
    int lane = threadIdx.x & 31;
    if (gw >= BS) return;
    int b = gw >> 10;
    int i = gw & (Ss - 1);
    const __nv_bfloat16* ui = g_uh + (size_t)gw * Hh;
    int padi = mask[(b << 10) + i];
    float su = -1e9f, sd = -1e9f;
    float bb = g_bqbk;

    bool up = (i < Ss - 1) && padi && mask[(b << 10) + i + 1];
    bool dn = (i > 0)      && padi && mask[(b << 10) + i - 1];

    float vq = 0.f;
    if (up || dn) vq = dot_cn_wqb(g_cnh + (size_t)gw * Hh, lane);

    if (up) {
        float du, vkb;
        dot2_u_wkb(ui, g_cnh + (size_t)(gw + 1) * Hh, lane, du, vkb);
        su = (du + vq + vkb + bb) * (1.0f / 32.0f);
    }
    if (dn) {
        float du, vkb;
        dot2_u_wkb(ui, g_cnh + (size_t)(gw - 1) * Hh, lane, du, vkb);
        sd = (du + vq + vkb + bb) * (1.0f / 32.0f);
    }
    if (lane == 0) { g_sup[gw] = su; g_sdn[gw] = sd; }
}

// ---------------- probs helper ----------------
__device__ __forceinline__ float2 probs2(float su, float sd) {
    float m = fmaxf(su, sd);
    float eu = expf(su - m), ed = expf(sd - m);
    float z = eu + ed;
    return make_float2(eu / z, ed / z);   // (pup, pdn)
}

// ---------------- fused output (band inline): one block per (b,row) ----------------
__global__ __launch_bounds__(256) void out_kernel(const float* __restrict__ prior,
                                                  const int* __restrict__ mask,
                                                  float* __restrict__ out,
                                                  int Nout) {
    int row = blockIdx.x;
    int b = row >> 10;
    int r = row & (Ss - 1);
    int tid = threadIdx.x;
    const float c0 = sqrtf(1e-9f);
    int base_b = b << 10;

    // inline band values for this row (band[i] = sqrt(pup(i)*pdn(i+1)+1e-9))
    float bandm = c0, bandp = c0;
    if (r > 0) {
        float2 p0 = probs2(g_sup[base_b + r - 1], g_sdn[base_b + r - 1]);
        float2 p1 = probs2(g_sup[base_b + r],     g_sdn[base_b + r]);
        bandm = sqrtf(p0.x * p1.y + 1e-9f);
    }
    if (r < Ss - 1) {
        float2 p1 = probs2(g_sup[base_b + r],     g_sdn[base_b + r]);
        float2 p2 = probs2(g_sup[base_b + r + 1], g_sdn[base_b + r + 1]);
        bandp = sqrtf(p1.x * p2.y + 1e-9f);
    }

    float4 p4 = ((const float4*)(prior + (size_t)row * Ss))[tid];
    int4  m4 = ((const int4*)(mask + base_b))[tid];
    int padr = mask[base_b + r];

    float pv[4] = {p4.x, p4.y, p4.z, p4.w};
    int   mc[4] = {m4.x, m4.y, m4.z, m4.w};
    int c_base = tid * 4;

    float nbo[4], graw[4];
    #pragma unroll
    for (int j = 0; j < 4; j++) {
        int c = c_base + j;
        float nbs = c0;
        if (r > 0 && c == r - 1)       nbs = bandm;
        if (r < Ss - 1 && c == r + 1)  nbs = bandp;
        nbo[j]  = pv[j] + (1.0f - pv[j]) * nbs;
        graw[j] = (c == r) ? (2.0f + 1e-9f) : (1.0f + nbo[j]);
    }

    __shared__ float red[8];
    float s = graw[0] + graw[1] + graw[2] + graw[3];
    #pragma unroll
    for (int o = 16; o; o >>= 1) s += __shfl_xor_sync(0xffffffffu, s, o);
    if ((tid & 31) == 0) red[tid >> 5] = s;
    __syncthreads();
    if (tid < 8) {
        float t = red[tid];
        #pragma unroll
        for (int o = 4; o; o >>= 1) t += __shfl_xor_sync(0xffu, t, o);
        if (tid == 0) red[0] = t;
    }
    __syncthreads();
    float invD = 1.0f / (red[0] + 1e-9f);

    float4 go, no;
    float f0 = (padr && mc[0]) ? 1.0f : 0.0f;
    float f1 = (padr && mc[1]) ? 1.0f : 0.0f;
    float f2 = (padr && mc[2]) ? 1.0f : 0.0f;
    float f3 = (padr && mc[3]) ? 1.0f : 0.0f;
    go.x = graw[0] * invD * f0; no.x = nbo[0] * f0;
    go.y = graw[1] * invD * f1; no.y = nbo[1] * f1;
    go.z = graw[2] * invD * f2; no.z = nbo[2] * f2;
    go.w = graw[3] * invD * f3; no.w = nbo[3] * f3;

    size_t base = (size_t)row * Ss + c_base;
    *(float4*)(out + base)                = go;
    *(float4*)(out + (size_t)Nout + base) = no;
}

// ---------------- launch ----------------
extern "C" void kernel_launch(void* const* d_in, const int* in_sizes, int n_in,
                              void* d_out, int out_size) {
    const float* context = (const float*)d_in[0];
    const int*   mask    = (const int*)  d_in[1];
    const float* prior   = (const float*)d_in[2];
    const float* gamma   = (const float*)d_in[3];
    const float* beta    = (const float*)d_in[4];
    const float* Wk      = (const float*)d_in[5];
    const float* bk      = (const float*)d_in[6];
    const float* Wq      = (const float*)d_in[7];
    const float* bq      = (const float*)d_in[8];
    float* out = (float*)d_out;
    int Nout = out_size / 2;

    __nv_bfloat16 *cnh, *wkh, *wqh, *Ath, *uh;
    cudaGetSymbolAddress((void**)&cnh, g_cnh);
    cudaGetSymbolAddress((void**)&wkh, g_wkh);
    cudaGetSymbolAddress((void**)&wqh, g_wqh);
    cudaGetSymbolAddress((void**)&Ath, g_Ath);
    cudaGetSymbolAddress((void**)&uh,  g_uh);

    static int smem_set = 0;
    if (!smem_set) {
        cudaFuncSetAttribute(gemm_bf16_nt,   cudaFuncAttributeMaxDynamicSharedMemorySize, 98304);
        cudaFuncSetAttribute(gemm_bf16_nt64, cudaFuncAttributeMaxDynamicSharedMemorySize, 49152);
        smem_set = 1;
    }

    // merged LN + weight convert / bias dots
    ln_conv_kernel<<<BS + 257, 256>>>(context, gamma, beta, Wq, bk, Wk, bq);

    // At[e,d] = sum_h Wk[e,h] * Wq[d,h]   (bf16 out, 64x64 tiles -> 256 CTAs)
    dim3 gsmall(Hh / 64, Hh / 64);
    gemm_bf16_nt64<<<gsmall, 128, 49152>>>(wkh, wqh, Ath, Hh, Hh);

    // u[i,e] = sum_d cn[i,d] * At[e,d]    (bf16 out, ldmatrix + frag DB, 2 CTA/SM)
    dim3 gbig(Hh / 128, BS / 128);
    gemm_bf16_nt<<<gbig, 256, 98304>>>(cnh, Ath, uh, Hh, Hh);

    // adjacent-pair scores with vq/vk folded in
    band_dots_kernel<<<(BS * 32) / 256, 256>>>(mask);

    // fused output with inline band
    out_kernel<<<BS, 256>>>(prior, mask, out, Nout);
}

// round 17
// speedup vs baseline: 7.2321x; 1.0477x over previous
#include <cuda_runtime.h>
#include <cuda_bf16.h>
#include <math.h>
#include <stdint.h>

#define Bb 8
#define Ss 1024
#define Hh 1024
#define BS (Bb*Ss)   // 8192

// ---------------- scratch (device globals; no allocation allowed) ----------------
__device__ __nv_bfloat16  g_cnh[(size_t)BS*Hh];   // layernorm output (bf16)
__device__ __nv_bfloat16  g_uh [(size_t)BS*Hh];   // u = cn @ (Wq Wk^T)  (bf16)
__device__ __nv_bfloat16  g_wkh[(size_t)Hh*Hh];
__device__ __nv_bfloat16  g_wqh[(size_t)Hh*Hh];
__device__ __nv_bfloat16  g_Ath[(size_t)Hh*Hh];   // At = Wk @ Wq^T (bf16)
__device__ float g_wqb[Hh];              // Wq @ bk
__device__ float g_wkb[Hh];              // Wk @ bq
__device__ float g_bqbk;
__device__ float g_sup[BS];
__device__ float g_sdn[BS];

// ================= helpers =================
__device__ __forceinline__ uint32_t smem_u32(const void* p) {
    uint32_t a;
    asm("{ .reg .u64 t; cvta.to.shared.u64 t, %1; cvt.u32.u64 %0, t; }" : "=r"(a) : "l"(p));
    return a;
}
__device__ __forceinline__ void cp16(uint32_t dst, const void* src) {
    asm volatile("cp.async.cg.shared.global [%0], [%1], 16;\n" :: "r"(dst), "l"(src));
}
#define MMA_BF16(d, a, b)                                                     \
    asm volatile("mma.sync.aligned.m16n8k16.row.col.f32.bf16.bf16.f32 "       \
                 "{%0,%1,%2,%3},{%4,%5,%6,%7},{%8,%9},{%0,%1,%2,%3};\n"       \
                 : "+f"(d[0]), "+f"(d[1]), "+f"(d[2]), "+f"(d[3])             \
                 : "r"(a[0]), "r"(a[1]), "r"(a[2]), "r"(a[3]),                \
                   "r"(b[0]), "r"(b[1]))
#define LDSM_X4(r0, r1, r2, r3, addr)                                         \
    asm volatile("ldmatrix.sync.aligned.m8n8.x4.shared.b16 {%0,%1,%2,%3}, [%4];" \
                 : "=r"(r0), "=r"(r1), "=r"(r2), "=r"(r3) : "r"(addr))

// ---------------- merged LayerNorm + weight-convert/bias kernel ----------------
__global__ __launch_bounds__(256) void ln_conv_kernel(const float* __restrict__ x,
                                                      const float* __restrict__ gamma,
                                                      const float* __restrict__ beta,
                                                      const float* __restrict__ Wq,
                                                      const float* __restrict__ bk,
                                                      const float* __restrict__ Wk,
                                                      const float* __restrict__ bq) {
    int tid = threadIdx.x;
    int lane = tid & 31;

    if (blockIdx.x < BS) {
        int row = blockIdx.x;
        const float4* xr = (const float4*)(x + (size_t)row * Hh);
        float4 v = xr[tid];

        __shared__ float red[8];
        float s = v.x + v.y + v.z + v.w;
        #pragma unroll
        for (int o = 16; o; o >>= 1) s += __shfl_xor_sync(0xffffffffu, s, o);
        if ((tid & 31) == 0) red[tid >> 5] = s;
        __syncthreads();
        if (tid < 8) {
            float t = red[tid];
            #pragma unroll
            for (int o = 4; o; o >>= 1) t += __shfl_xor_sync(0xffu, t, o);
            if (tid == 0) red[0] = t;
        }
        __syncthreads();
        float mu = red[0] * (1.0f / Hh);
        __syncthreads();
        float dx = v.x - mu, dy = v.y - mu, dz = v.z - mu, dw = v.w - mu;
        float ss = dx*dx + dy*dy + dz*dz + dw*dw;
        #pragma unroll
        for (int o = 16; o; o >>= 1) ss += __shfl_xor_sync(0xffffffffu, ss, o);
        if ((tid & 31) == 0) red[tid >> 5] = ss;
        __syncthreads();
        if (tid < 8) {
            float t = red[tid];
            #pragma unroll
            for (int o = 4; o; o >>= 1) t += __shfl_xor_sync(0xffu, t, o);
            if (tid == 0) red[0] = t;
        }
        __syncthreads();
        float var = red[0] * (1.0f / Hh);
        float rstd = rsqrtf(var + 1e-5f);

        float4 gm = ((const float4*)gamma)[tid];
        float4 bt = ((const float4*)beta)[tid];
        float ox = dx * rstd * gm.x + bt.x;
        float oy = dy * rstd * gm.y + bt.y;
        float oz = dz * rstd * gm.z + bt.z;
        float ow = dw * rstd * gm.w + bt.w;

        __nv_bfloat162* ch = (__nv_bfloat162*)(g_cnh + (size_t)row * Hh);
        ch[2 * tid]     = __floats2bfloat162_rn(ox, oy);
        ch[2 * tid + 1] = __floats2bfloat162_rn(oz, ow);
        return;
    }

    // convbias part
    int gw = (blockIdx.x - BS) * 8 + (tid >> 5);
    if (gw > 2048) return;

    if (gw == 2048) {
        float acc = 0.f;
        #pragma unroll
        for (int it = 0; it < 8; it++) {
            int c = it * 128 + lane * 4;
            float4 a = *(const float4*)(bq + c);
            float4 v = *(const float4*)(bk + c);
            acc += a.x * v.x + a.y * v.y + a.z * v.z + a.w * v.w;
        }
        #pragma unroll
        for (int o = 16; o; o >>= 1) acc += __shfl_xor_sync(0xffffffffu, acc, o);
        if (lane == 0) g_bqbk = acc;
        return;
    }

    const float* row; const float* vec; __nv_bfloat16* dsth;
    int r;
    if (gw < 1024) { r = gw;        row = Wq + (size_t)r * Hh; vec = bk; dsth = g_wqh + (size_t)r * Hh; }
    else           { r = gw - 1024; row = Wk + (size_t)r * Hh; vec = bq; dsth = g_wkh + (size_t)r * Hh; }

    float acc = 0.f;
    #pragma unroll
    for (int it = 0; it < 8; it++) {
        int c = it * 128 + lane * 4;
        float4 a = *(const float4*)(row + c);
        float4 v = *(const float4*)(vec + c);
        acc += a.x * v.x + a.y * v.y + a.z * v.z + a.w * v.w;
        __nv_bfloat162* d2 = (__nv_bfloat162*)(dsth + c);
        d2[0] = __floats2bfloat162_rn(a.x, a.y);
        d2[1] = __floats2bfloat162_rn(a.z, a.w);
    }
    #pragma unroll
    for (int o = 16; o; o >>= 1) acc += __shfl_xor_sync(0xffffffffu, acc, o);
    if (lane == 0) {
        if (gw < 1024) g_wqb[r] = acc;
        else           g_wkb[r] = acc;
    }
}

// ---------------- bf16 NT GEMM, 128x128 tile, 8 warps, 3-stage, ldmatrix, frag DB, 2 CTA/SM ----------------
__global__ void __launch_bounds__(256, 2) gemm_bf16_nt(const __nv_bfloat16* __restrict__ Aop,
                                                       const __nv_bfloat16* __restrict__ Bop,
                                                       __nv_bfloat16* __restrict__ C,
                                                       int N, int K) {
    extern __shared__ uint32_t smemw[];
    int tid = threadIdx.x;
    int lane = tid & 31, warp = tid >> 5;
    int wy = warp >> 2, wx = warp & 3;

    const __nv_bfloat16* Abase = Aop + (size_t)blockIdx.y * 128 * K;
    const __nv_bfloat16* Bbase = Bop + (size_t)blockIdx.x * 128 * K;

    uint32_t sbase = smem_u32(smemw);
    const uint32_t STAGEB = 32768u;

    float acc[4][4][4];
    #pragma unroll
    for (int i = 0; i < 4; i++)
        #pragma unroll
        for (int j = 0; j < 4; j++)
            #pragma unroll
            for (int r = 0; r < 4; r++) acc[i][j][r] = 0.f;

    int mrow = tid >> 3;
    int c4   = tid & 7;
    int c4x  = c4 ^ (mrow & 7);
    const __nv_bfloat16* Asrc = Abase + (size_t)mrow * K + 8 * c4;
    const __nv_bfloat16* Bsrc = Bbase + (size_t)mrow * K + 8 * c4;
    uint32_t Adst = sbase + (uint32_t)(mrow * 128 + c4x * 16);
    uint32_t Bdst = Adst + 16384u;

    int ntiles = K >> 6;

    auto load_stage = [&](int slot, int k0) {
        uint32_t so = (uint32_t)slot * STAGEB;
        #pragma unroll
        for (int r = 0; r < 4; r++) {
            cp16(Adst + so + (uint32_t)r * 4096u, Asrc + (size_t)(32 * r) * K + k0);
            cp16(Bdst + so + (uint32_t)r * 4096u, Bsrc + (size_t)(32 * r) * K + k0);
        }
        asm volatile("cp.async.commit_group;\n");
    };

    load_stage(0, 0);
    load_stage(1, 64);

    int sel = lane >> 3, ri = lane & 7;
    int gselA = sel >> 1;
    int gselB = sel & 1;
    uint32_t rowA[4], rowB[2];
    #pragma unroll
    for (int mt = 0; mt < 4; mt++) {
        int rA = wy * 64 + mt * 16 + (sel & 1) * 8 + ri;
        rowA[mt] = (uint32_t)(rA * 128);
    }
    #pragma unroll
    for (int p = 0; p < 2; p++) {
        int rB = wx * 32 + p * 16 + (sel >> 1) * 8 + ri;
        rowB[p] = 16384u + (uint32_t)(rB * 128);
    }

    uint32_t afr[2][4][4], bfr[2][4][2];

    for (int t = 0; t < ntiles; t++) {
        if (t + 1 < ntiles) asm volatile("cp.async.wait_group 1;\n" ::: "memory");
        else                asm volatile("cp.async.wait_group 0;\n" ::: "memory");
        __syncthreads();

        if (t + 2 < ntiles) load_stage((t + 2) % 3, (t + 2) * 64);

        uint32_t sb = sbase + (uint32_t)(t % 3) * STAGEB;

        auto ldfr = [&](int kkstep, int buf) {
            int kk2 = kkstep * 2;
            uint32_t offA = (uint32_t)(((kk2 + gselA) ^ ri) << 4);
            uint32_t offB = (uint32_t)(((kk2 + gselB) ^ ri) << 4);
            #pragma unroll
            for (int mt = 0; mt < 4; mt++)
                LDSM_X4(afr[buf][mt][0], afr[buf][mt][1], afr[buf][mt][2], afr[buf][mt][3],
                        sb + rowA[mt] + offA);
            #pragma unroll
            for (int p = 0; p < 2; p++)
                LDSM_X4(bfr[buf][2*p][0], bfr[buf][2*p][1], bfr[buf][2*p+1][0], bfr[buf][2*p+1][1],
                        sb + rowB[p] + offB);
        };

        ldfr(0, 0);
        #pragma unroll
        for (int kkstep = 0; kkstep < 4; kkstep++) {
            int cur = kkstep & 1;
            if (kkstep < 3) ldfr(kkstep + 1, cur ^ 1);
            #pragma unroll
            for (int mt = 0; mt < 4; mt++)
                #pragma unroll
                for (int nt = 0; nt < 4; nt++)
                    MMA_BF16(acc[mt][nt], afr[cur][mt], bfr[cur][nt]);
        }
    }

    #pragma unroll
    for (int mt = 0; mt < 4; mt++) {
        int r0 = blockIdx.y * 128 + wy * 64 + mt * 16 + (lane >> 2);
        #pragma unroll
        for (int nt = 0; nt < 4; nt++) {
            int cc = blockIdx.x * 128 + wx * 32 + nt * 8 + 2 * (lane & 3);
            *(__nv_bfloat162*)(C + (size_t)r0 * N + cc) =
                __floats2bfloat162_rn(acc[mt][nt][0], acc[mt][nt][1]);
            *(__nv_bfloat162*)(C + (size_t)(r0 + 8) * N + cc) =
                __floats2bfloat162_rn(acc[mt][nt][2], acc[mt][nt][3]);
        }
    }
}

// ---------------- bf16 NT GEMM, 64x64 tile, 4 warps, 3-stage; bf16 out (small GEMM) ----------------
__global__ __launch_bounds__(128) void gemm_bf16_nt64(const __nv_bfloat16* __restrict__ Aop,
                                                      const __nv_bfloat16* __restrict__ Bop,
                                                      __nv_bfloat16* __restrict__ C,
                                                      int N, int K) {
    extern __shared__ uint32_t smemw[];
    const int STAGEW = 4096;
    int tid = threadIdx.x;
    int lane = tid & 31, warp = tid >> 5;
    int wy = warp >> 1, wx = warp & 1;

    const __nv_bfloat16* Abase = Aop + (size_t)blockIdx.y * 64 * K;
    const __nv_bfloat16* Bbase = Bop + (size_t)blockIdx.x * 64 * K;

    uint32_t sbase = smem_u32(smemw);

    float acc[2][4][4];
    #pragma unroll
    for (int i = 0; i < 2; i++)
        #pragma unroll
        for (int j = 0; j < 4; j++)
            #pragma unroll
            for (int r = 0; r < 4; r++) acc[i][j][r] = 0.f;

    int mrow = tid >> 3;
    int c4   = tid & 7;
    int c4x  = c4 ^ (mrow & 7);
    const __nv_bfloat16* Asrc = Abase + (size_t)mrow * K + 8 * c4;
    const __nv_bfloat16* Bsrc = Bbase + (size_t)mrow * K + 8 * c4;
    uint32_t Adst = sbase + (uint32_t)(mrow * 32 + 4 * c4x) * 4u;
    uint32_t Bdst = Adst + 8192u;
    const uint32_t STAGEB = 16384u;

    int ntiles = K >> 6;

    auto load_stage = [&](int slot, int k0) {
        uint32_t so = (uint32_t)slot * STAGEB;
        #pragma unroll
        for (int r = 0; r < 4; r++) {
            cp16(Adst + so + (uint32_t)r * 2048u, Asrc + (size_t)(16 * r) * K + k0);
            cp16(Bdst + so + (uint32_t)r * 2048u, Bsrc + (size_t)(16 * r) * K + k0);
        }
        asm volatile("cp.async.commit_group;\n");
    };

    load_stage(0, 0);
    load_stage(1, 64);

    int q = lane >> 2, rsel = lane & 3;
    int sw = 4 * q;

    for (int t = 0; t < ntiles; t++) {
        if (t + 1 < ntiles) asm volatile("cp.async.wait_group 1;\n" ::: "memory");
        else                asm volatile("cp.async.wait_group 0;\n" ::: "memory");
        __syncthreads();

        if (t + 2 < ntiles) load_stage((t + 2) % 3, (t + 2) * 64);

        int cur = t % 3;
        const uint32_t* sA = smemw + cur * STAGEW;
        const uint32_t* sB = sA + 2048;

        #pragma unroll
        for (int kk = 0; kk < 32; kk += 8) {
            int col0 = (kk + rsel) ^ sw;
            int col1 = col0 ^ 4;
            uint32_t a[2][4], b[4][2];
            #pragma unroll
            for (int mt = 0; mt < 2; mt++) {
                int m0 = wy * 32 + mt * 16 + q;
                a[mt][0] = sA[m0 * 32 + col0];
                a[mt][1] = sA[(m0 + 8) * 32 + col0];
                a[mt][2] = sA[m0 * 32 + col1];
                a[mt][3] = sA[(m0 + 8) * 32 + col1];
            }
            #pragma unroll
            for (int nt = 0; nt < 4; nt++) {
                int n0 = wx * 32 + nt * 8 + q;
                b[nt][0] = sB[n0 * 32 + col0];
                b[nt][1] = sB[n0 * 32 + col1];
            }
            #pragma unroll
            for (int mt = 0; mt < 2; mt++)
                #pragma unroll
                for (int nt = 0; nt < 4; nt++)
                    MMA_BF16(acc[mt][nt], a[mt], b[nt]);
        }
    }

    #pragma unroll
    for (int mt = 0; mt < 2; mt++) {
        int r0 = blockIdx.y * 64 + wy * 32 + mt * 16 + (lane >> 2);
        #pragma unroll
        for (int nt = 0; nt < 4; nt++) {
            int cc = blockIdx.x * 64 + wx * 32 + nt * 8 + 2 * (lane & 3);
            *(__nv_bfloat162*)(C + (size_t)r0 * N + cc) =
                __floats2bfloat162_rn(acc[mt][nt][0], acc[mt][nt][1]);
            *(__nv_bfloat162*)(C + (size_t)(r0 + 8) * N + cc) =
                __floats2bfloat162_rn(acc[mt][nt][2], acc[mt][nt][3]);
        }
    }
}

// ---------------- single-pass adjacent-pair scores: one warp per (b,i) ----------------
// Computes all 5 dots in one streaming loop: u.cn_{i+1}, u.cn_{i-1},
// cn_i.wqb, cn_{i+1}.wkb, cn_{i-1}.wkb. Neighbor pointers clamped; validity
// applied afterward via mask flags.
__global__ __launch_bounds__(256) void band_dots_kernel(const int* __restrict__ mask) {
    int gw = (blockIdx.x * blockDim.x + threadIdx.x) >> 5;
    int lane = threadIdx.x & 31;
    if (gw >= BS) return;
    int b = gw >> 10;
    int i = gw & (Ss - 1);
    int padi = mask[(b << 10) + i];

    bool up = (i < Ss - 1) && padi && mask[(b << 10) + i + 1];
    bool dn = (i > 0)      && padi && mask[(b << 10) + i - 1];

    float su = -1e9f, sd = -1e9f;

    if (up || dn) {
        const __nv_bfloat16* ui = g_uh  + (size_t)gw * Hh;
        const __nv_bfloat16* ci = g_cnh + (size_t)gw * Hh;
        const __nv_bfloat16* cp = g_cnh + (size_t)(up ? gw + 1 : gw) * Hh;
        const __nv_bfloat16* cm = g_cnh + (size_t)(dn ? gw - 1 : gw) * Hh;

        float dup = 0.f, ddn = 0.f, vq = 0.f, vkp = 0.f, vkm = 0.f;
        #pragma unroll
        for (int it = 0; it < 4; it++) {
            int c = it * 256 + lane * 8;
            uint4 uw  = *(const uint4*)(ui + c);
            uint4 ciw = *(const uint4*)(ci + c);
            uint4 cpw = *(const uint4*)(cp + c);
            uint4 cmw = *(const uint4*)(cm + c);
            float4 q0 = *(const float4*)(g_wqb + c);
            float4 q1 = *(const float4*)(g_wqb + c + 4);
            float4 k0 = *(const float4*)(g_wkb + c);
            float4 k1 = *(const float4*)(g_wkb + c + 4);
            const __nv_bfloat162* u2  = (const __nv_bfloat162*)&uw;
            const __nv_bfloat162* ci2 = (const __nv_bfloat162*)&ciw;
            const __nv_bfloat162* cp2 = (const __nv_bfloat162*)&cpw;
            const __nv_bfloat162* cm2 = (const __nv_bfloat162*)&cmw;
            float wq[8] = {q0.x, q0.y, q0.z, q0.w, q1.x, q1.y, q1.z, q1.w};
            float wk[8] = {k0.x, k0.y, k0.z, k0.w, k1.x, k1.y, k1.z, k1.w};
            #pragma unroll
            for (int j = 0; j < 4; j++) {
                float2 fu = __bfloat1622float2(u2[j]);
                float2 fi = __bfloat1622float2(ci2[j]);
                float2 fp = __bfloat1622float2(cp2[j]);
                float2 fm = __bfloat1622float2(cm2[j]);
                dup += fu.x * fp.x + fu.y * fp.y;
                ddn += fu.x * fm.x + fu.y * fm.y;
                vq  += fi.x * wq[2*j] + fi.y * wq[2*j + 1];
                vkp += fp.x * wk[2*j] + fp.y * wk[2*j + 1];
                vkm += fm.x * wk[2*j] + fm.y * wk[2*j + 1];
            }
        }
        #pragma unroll
        for (int o = 16; o; o >>= 1) {
            dup += __shfl_xor_sync(0xffffffffu, dup, o);
            ddn += __shfl_xor_sync(0xffffffffu, ddn, o);
            vq  += __shfl_xor_sync(0xffffffffu, vq,  o);
            vkp += __shfl_xor_sync(0xffffffffu, vkp, o);
            vkm += __shfl_xor_sync(0xffffffffu, vkm, o);
        }
        float bb = g_bqbk;
        if (up) su = (dup + vq + vkp + bb) * (1.0f / 32.0f);
        if (dn) sd = (ddn + vq + vkm + bb) * (1.0f / 32.0f);
    }
    if (lane == 0) { g_sup[gw] = su; g_sdn[gw] = sd; }
}

// ---------------- probs helper ----------------
__device__ __forceinline__ float2 probs2(float su, float sd) {
    float m = fmaxf(su, sd);
    float eu = expf(su - m), ed = expf(sd - m);
    float z = eu + ed;
    return make_float2(eu / z, ed / z);   // (pup, pdn)
}

// ---------------- fused output (band inline): one block per (b,row) ----------------
__global__ __launch_bounds__(256) void out_kernel(const float* __restrict__ prior,
                                                  const int* __restrict__ mask,
                                                  float* __restrict__ out,
                                                  int Nout) {
    int row = blockIdx.x;
    int b = row >> 10;
    int r = row & (Ss - 1);
    int tid = threadIdx.x;
    const float c0 = sqrtf(1e-9f);
    int base_b = b << 10;

    // inline band values for this row (band[i] = sqrt(pup(i)*pdn(i+1)+1e-9))
    float2 p1 = probs2(g_sup[base_b + r], g_sdn[base_b + r]);
    float bandm = c0, bandp = c0;
    if (r > 0) {
        float2 p0 = probs2(g_sup[base_b + r - 1], g_sdn[base_b + r - 1]);
        bandm = sqrtf(p0.x * p1.y + 1e-9f);
    }
    if (r < Ss - 1) {
        float2 p2 = probs2(g_sup[base_b + r + 1], g_sdn[base_b + r + 1]);
        bandp = sqrtf(p1.x * p2.y + 1e-9f);
    }

    float4 p4 = ((const float4*)(prior + (size_t)row * Ss))[tid];
    int4  m4 = ((const int4*)(mask + base_b))[tid];
    int padr = mask[base_b + r];

    float pv[4] = {p4.x, p4.y, p4.z, p4.w};
    int   mc[4] = {m4.x, m4.y, m4.z, m4.w};
    int c_base = tid * 4;

    float nbo[4], graw[4];
    #pragma unroll
    for (int j = 0; j < 4; j++) {
        int c = c_base + j;
        float nbs = c0;
        if (r > 0 && c == r - 1)       nbs = bandm;
        if (r < Ss - 1 && c == r + 1)  nbs = bandp;
        nbo[j]  = pv[j] + (1.0f - pv[j]) * nbs;
        graw[j] = (c == r) ? (2.0f + 1e-9f) : (1.0f + nbo[j]);
    }

    __shared__ float red[8];
    float s = graw[0] + graw[1] + graw[2] + graw[3];
    #pragma unroll
    for (int o = 16; o; o >>= 1) s += __shfl_xor_sync(0xffffffffu, s, o);
    if ((tid & 31) == 0) red[tid >> 5] = s;
    __syncthreads();
    if (tid < 8) {
        float t = red[tid];
        #pragma unroll
        for (int o = 4; o; o >>= 1) t += __shfl_xor_sync(0xffu, t, o);
        if (tid == 0) red[0] = t;
    }
    __syncthreads();
    float invD = 1.0f / (red[0] + 1e-9f);

    float4 go, no;
    float f0 = (padr && mc[0]) ? 1.0f : 0.0f;
    float f1 = (padr && mc[1]) ? 1.0f : 0.0f;
    float f2 = (padr && mc[2]) ? 1.0f : 0.0f;
    float f3 = (padr && mc[3]) ? 1.0f : 0.0f;
    go.x = graw[0] * invD * f0; no.x = nbo[0] * f0;
    go.y = graw[1] * invD * f1; no.y = nbo[1] * f1;
    go.z = graw[2] * invD * f2; no.z = nbo[2] * f2;
    go.w = graw[3] * invD * f3; no.w = nbo[3] * f3;

    size_t base = (size_t)row * Ss + c_base;
    *(float4*)(out + base)                = go;
    *(float4*)(out + (size_t)Nout + base) = no;
}

// ---------------- launch ----------------
extern "C" void kernel_launch(void* const* d_in, const int* in_sizes, int n_in,
                              void* d_out, int out_size) {
    const float* context = (const float*)d_in[0];
    const int*   mask    = (const int*)  d_in[1];
    const float* prior   = (const float*)d_in[2];
    const float* gamma   = (const float*)d_in[3];
    const float* beta    = (const float*)d_in[4];
    const float* Wk      = (const float*)d_in[5];
    const float* bk      = (const float*)d_in[6];
    const float* Wq      = (const float*)d_in[7];
    const float* bq      = (const float*)d_in[8];
    float* out = (float*)d_out;
    int Nout = out_size / 2;

    __nv_bfloat16 *cnh, *wkh, *wqh, *Ath, *uh;
    cudaGetSymbolAddress((void**)&cnh, g_cnh);
    cudaGetSymbolAddress((void**)&wkh, g_wkh);
    cudaGetSymbolAddress((void**)&wqh, g_wqh);
    cudaGetSymbolAddress((void**)&Ath, g_Ath);
    cudaGetSymbolAddress((void**)&uh,  g_uh);

    static int smem_set = 0;
    if (!smem_set) {
        cudaFuncSetAttribute(gemm_bf16_nt,   cudaFuncAttributeMaxDynamicSharedMemorySize, 98304);
        cudaFuncSetAttribute(gemm_bf16_nt64, cudaFuncAttributeMaxDynamicSharedMemorySize, 49152);
        smem_set = 1;
    }

    // merged LN + weight convert / bias dots
    ln_conv_kernel<<<BS + 257, 256>>>(context, gamma, beta, Wq, bk, Wk, bq);

    // At[e,d] = sum_h Wk[e,h] * Wq[d,h]   (bf16 out, 64x64 tiles -> 256 CTAs)
    dim3 gsmall(Hh / 64, Hh / 64);
    gemm_bf16_nt64<<<gsmall, 128, 49152>>>(wkh, wqh, Ath, Hh, Hh);

    // u[i,e] = sum_d cn[i,d] * At[e,d]    (bf16 out, ldmatrix + frag DB, 2 CTA/SM)
    dim3 gbig(Hh / 128, BS / 128);
    gemm_bf16_nt<<<gbig, 256, 98304>>>(cnh, Ath, uh, Hh, Hh);

    // single-pass adjacent-pair scores
    band_dots_kernel<<<(BS * 32) / 256, 256>>>(mask);

    // fused output with inline band
    out_kernel<<<BS, 256>>>(prior, mask, out, Nout);
}